// round 8
// baseline (speedup 1.0000x reference)
#include <cuda_runtime.h>
#include <math.h>
#include <stdint.h>

#define D 128
#define NMAX 100000
#define EMAX 1000000
#define SECT 256
#define QSECT 32                 // sectors per smem octant (2*32*128*4B = 32 KB)
#define NQ 8                     // octant passes

#define PI_F      3.14159265358979f
#define HALFPI_F  1.57079632679490f
#define TWOPI_F   6.28318530717959f

// ---------------- scratch (static device globals; no runtime alloc) ------------
__device__ float g_acc[(size_t)NMAX * D];   // 51.2 MB scatter accumulator
__device__ float g_cnt[NMAX];               // per-dst edge counts
__device__ float g_bounds[SECT];            // sorted sector boundary angles
__device__ float g_U[SECT * D];             // sector tables: pe = w0*U[s] + w1*V[s]
__device__ float g_V[SECT * D];
__device__ float g_colsum[D];               // BN stats
__device__ float g_colsq[D];
__device__ int   g_ei64;                    // 1 if edge_index is int64
__device__ int   g_src[EMAX];               // precomputed per-edge metadata
__device__ int   g_dst[EMAX];
__device__ unsigned char g_sct[EMAX];

// ---------------- K-1: detect edge_index dtype ---------------------------------
__global__ void k_detect(const int* __restrict__ w) {
    if (threadIdx.x == 0 && blockIdx.x == 0) {
        int all0 = 1;
        #pragma unroll
        for (int j = 1; j < 64; j += 2) all0 &= (w[j] == 0);
        g_ei64 = all0;
    }
}

// ---------------- K0: zero scratch ---------------------------------------------
__global__ void k_zero(int n) {
    int nd4 = n * (D / 4);
    float4 z = make_float4(0.f, 0.f, 0.f, 0.f);
    int stride = gridDim.x * blockDim.x;
    for (int i = blockIdx.x * blockDim.x + threadIdx.x; i < nd4; i += stride)
        reinterpret_cast<float4*>(g_acc)[i] = z;
    for (int i = blockIdx.x * blockDim.x + threadIdx.x; i < n; i += stride)
        g_cnt[i] = 0.f;
    if (blockIdx.x == 0 && threadIdx.x < D) {
        g_colsum[threadIdx.x] = 0.f;
        g_colsq[threadIdx.x]  = 0.f;
    }
}

// ---------------- K1: sector boundary angles ------------------------------------
__global__ void k_bounds(const float* __restrict__ pw1) {
    __shared__ float raw[SECT];
    int t = threadIdx.x;
    if (t < D) {
        float A = pw1[t];
        float B = pw1[D + t];
        float phi = atan2f(B, A);
        float c0 = phi + HALFPI_F; if (c0 >  PI_F) c0 -= TWOPI_F;
        float c1 = phi - HALFPI_F; if (c1 < -PI_F) c1 += TWOPI_F;
        raw[2 * t]     = c0;
        raw[2 * t + 1] = c1;
    }
    __syncthreads();
    float v = raw[t];
    int rank = 0;
    #pragma unroll 8
    for (int j = 0; j < SECT; j++) {
        float u = raw[j];
        rank += (u < v) || (u == v && j < t);
    }
    g_bounds[rank] = v;
}

// ---------------- K2: sector tables U,V ----------------------------------------
__global__ void k_sectors(const float* __restrict__ pw1, const float* __restrict__ pw2) {
    __shared__ float Am[D], Bm[D];
    __shared__ float thc_s;
    int s = blockIdx.x;
    int k = threadIdx.x;
    if (k == 0) {
        float b0 = g_bounds[s];
        float b1 = (s < SECT - 1) ? g_bounds[s + 1] : (g_bounds[0] + TWOPI_F);
        thc_s = 0.5f * (b0 + b1);
    }
    __syncthreads();
    float c = cosf(thc_s), sn = sinf(thc_s);
    float A = pw1[k], B = pw1[D + k];
    bool m = fmaf(A, c, B * sn) > 0.f;
    Am[k] = m ? A : 0.f;
    Bm[k] = m ? B : 0.f;
    __syncthreads();
    float u = 0.f, v = 0.f;
    #pragma unroll 8
    for (int d = 0; d < D; d++) {
        float w = pw2[d * D + k];
        u = fmaf(Am[d], w, u);
        v = fmaf(Bm[d], w, v);
    }
    g_U[s * D + k] = u;
    g_V[s * D + k] = v;
}

// ---------------- K3a: per-edge metadata precompute -----------------------------
// src/dst to int32, sector via atan2 + binary search (done ONCE per edge),
// plus the per-dst count atomic.
__global__ __launch_bounds__(256) void k_prep(const void* __restrict__ ei_raw,
                                              const float* __restrict__ ew, int E) {
    __shared__ float sbound[SECT];
    int t = threadIdx.x;
    sbound[t] = g_bounds[t];
    __syncthreads();
    const long long* ei64 = (const long long*)ei_raw;
    const int*       ei32 = (const int*)ei_raw;
    int is64 = g_ei64;
    int stride = gridDim.x * blockDim.x;
    for (int e = blockIdx.x * blockDim.x + t; e < E; e += stride) {
        int src, dst;
        if (is64) { src = (int)ei64[e]; dst = (int)ei64[E + e]; }
        else      { src = ei32[e];      dst = ei32[E + e]; }
        float2 wv = reinterpret_cast<const float2*>(ew)[e];
        float th = atan2f(wv.y, wv.x);
        int lo = 0, hi = SECT;
        while (lo < hi) {
            int mid = (lo + hi) >> 1;
            if (sbound[mid] <= th) lo = mid + 1; else hi = mid;
        }
        int sct = (lo == 0) ? (SECT - 1) : (lo - 1);
        g_src[e] = src;
        g_dst[e] = dst;
        g_sct[e] = (unsigned char)sct;
        atomicAdd(&g_cnt[dst], 1.f);
    }
}

// ---------------- K3b: edges — smem-resident octant tables, 8 passes ------------
// grid = (nchunks, NQ). Block (cx, q) holds U/V for sectors [q*32, q*32+32) in
// 32 KB static smem; processes only edges whose sector is in that octant.
__global__ __launch_bounds__(256) void k_edges(const float* __restrict__ x,
                                               const float* __restrict__ ew, int E) {
    __shared__ float sU[QSECT * D];
    __shared__ float sV[QSECT * D];
    int t = threadIdx.x;
    int q = blockIdx.y;
    int sbase = q * QSECT;
    for (int i = t; i < QSECT * D / 4; i += 256) {
        reinterpret_cast<float4*>(sU)[i] = reinterpret_cast<const float4*>(g_U + sbase * D)[i];
        reinterpret_cast<float4*>(sV)[i] = reinterpret_cast<const float4*>(g_V + sbase * D)[i];
    }
    __syncthreads();

    int lane = t & 31;
    int wid  = blockIdx.x * 8 + (t >> 5);
    int stride = gridDim.x * 8 * 32;

    for (int e0 = wid * 32; e0 < E; e0 += stride) {
        int e = e0 + lane;
        int src = 0, dst = 0, sct = -1;
        float w0 = 0.f, w1 = 0.f;
        bool valid = (e < E);
        if (valid) {
            sct = g_sct[e];
            if ((sct >> 5) == q) {
                src = g_src[e];
                dst = g_dst[e];
                float2 wv = reinterpret_cast<const float2*>(ew)[e];
                w0 = wv.x; w1 = wv.y;
            } else sct = -1;
        }
        unsigned mask = __ballot_sync(0xffffffffu, sct >= 0);
        while (mask) {
            int i = __ffs(mask) - 1;
            mask &= mask - 1;
            int   s  = __shfl_sync(0xffffffffu, src, i);
            int   dd = __shfl_sync(0xffffffffu, dst, i);
            int   sc = __shfl_sync(0xffffffffu, sct, i);
            float a0 = __shfl_sync(0xffffffffu, w0, i);
            float a1 = __shfl_sync(0xffffffffu, w1, i);

            float4 xj = __ldg(reinterpret_cast<const float4*>(x + (size_t)s * D) + lane);
            float4 u4 = reinterpret_cast<const float4*>(sU + (sc & (QSECT - 1)) * D)[lane];
            float4 v4 = reinterpret_cast<const float4*>(sV + (sc & (QSECT - 1)) * D)[lane];

            float4 m;
            m.x = xj.x * fmaf(a0, u4.x, fmaf(a1, v4.x, 1.f));
            m.y = xj.y * fmaf(a0, u4.y, fmaf(a1, v4.y, 1.f));
            m.z = xj.z * fmaf(a0, u4.z, fmaf(a1, v4.z, 1.f));
            m.w = xj.w * fmaf(a0, u4.w, fmaf(a1, v4.w, 1.f));

            float* p = g_acc + (size_t)dd * D + lane * 4;
            asm volatile("red.global.add.v4.f32 [%0], {%1, %2, %3, %4};"
                         :: "l"(p), "f"(m.x), "f"(m.y), "f"(m.z), "f"(m.w) : "memory");
        }
    }
}

// ---------------- tf32 helpers --------------------------------------------------
__device__ __forceinline__ void split_tf32(float a, float& hi, float& lo) {
    unsigned hb, lb;
    asm("cvt.rna.tf32.f32 %0, %1;" : "=r"(hb) : "f"(a));
    hi = __uint_as_float(hb);
    float r = a - hi;
    asm("cvt.rna.tf32.f32 %0, %1;" : "=r"(lb) : "f"(r));
    lo = __uint_as_float(lb);
}

__device__ __forceinline__ void mma_tf32(float* d, float a0, float a1, float a2, float a3,
                                         float b0, float b1) {
    asm volatile(
        "mma.sync.aligned.m16n8k8.row.col.f32.tf32.tf32.f32 "
        "{%0,%1,%2,%3}, {%4,%5,%6,%7}, {%8,%9}, {%0,%1,%2,%3};\n"
        : "+f"(d[0]), "+f"(d[1]), "+f"(d[2]), "+f"(d[3])
        : "r"(__float_as_uint(a0)), "r"(__float_as_uint(a1)),
          "r"(__float_as_uint(a2)), "r"(__float_as_uint(a3)),
          "r"(__float_as_uint(b0)), "r"(__float_as_uint(b1)));
}

// ---------------- K4: tensor-core GEMM [N,256]@[256,128], 3xTF32 ----------------
#define LDP 20
__global__ __launch_bounds__(256, 2) void k_gemm(const float* __restrict__ x,
                                                 const float* __restrict__ W,
                                                 const float* __restrict__ bias,
                                                 float* __restrict__ out, int N) {
    __shared__ float AsH[128 * LDP], AsL[128 * LDP];
    __shared__ float WsH[128 * LDP], WsL[128 * LDP];
    __shared__ float inv_s[128];
    __shared__ float scol[128], scolq[128];

    int tid = threadIdx.x;
    int row0 = blockIdx.x * 128;
    if (tid < 128) {
        int r = row0 + tid;
        inv_s[tid] = (r < N) ? (1.f / fmaxf(g_cnt[r], 1.f)) : 0.f;
        scol[tid] = 0.f; scolq[tid] = 0.f;
    }

    int lane  = tid & 31;
    int warp  = tid >> 5;
    int warpM = warp >> 2;
    int warpN = warp & 3;
    int grp   = lane >> 2;
    int th4   = lane & 3;

    float c[4][4][4];
    #pragma unroll
    for (int mi = 0; mi < 4; mi++)
        #pragma unroll
        for (int ni = 0; ni < 4; ni++)
            #pragma unroll
            for (int j = 0; j < 4; j++) c[mi][ni][j] = 0.f;

    __syncthreads();

    for (int kt = 0; kt < 16; kt++) {
        float4 av[2]; float ainv[2]; int am[2];
        float4 wv[2]; int wk[2], wn[2];
        #pragma unroll
        for (int u = 0; u < 2; u++) {
            int s = tid + u * 256;
            int m  = s >> 2, ch = s & 3;
            am[u] = m;
            int r = row0 + m;
            av[u] = make_float4(0.f, 0.f, 0.f, 0.f);
            ainv[u] = 1.f;
            if (r < N) {
                if (kt < 8) {
                    av[u] = *reinterpret_cast<const float4*>(x + (size_t)r * D + kt * 16 + ch * 4);
                } else {
                    av[u] = *reinterpret_cast<const float4*>(g_acc + (size_t)r * D + (kt - 8) * 16 + ch * 4);
                    ainv[u] = inv_s[m];
                }
            }
            int kr = s & 15, n4 = s >> 4;
            wk[u] = kr; wn[u] = n4;
            wv[u] = *reinterpret_cast<const float4*>(W + (size_t)(kt * 16 + kr) * D + n4 * 4);
        }

        __syncthreads();
        #pragma unroll
        for (int u = 0; u < 2; u++) {
            float iv = ainv[u];
            float h0, l0, h1, l1, h2, l2, h3, l3;
            split_tf32(av[u].x * iv, h0, l0);
            split_tf32(av[u].y * iv, h1, l1);
            split_tf32(av[u].z * iv, h2, l2);
            split_tf32(av[u].w * iv, h3, l3);
            int s = tid + u * 256;
            int base = am[u] * LDP + (s & 3) * 4;
            *reinterpret_cast<float4*>(&AsH[base]) = make_float4(h0, h1, h2, h3);
            *reinterpret_cast<float4*>(&AsL[base]) = make_float4(l0, l1, l2, l3);
            float wh, wl;
            split_tf32(wv[u].x, wh, wl); WsH[(wn[u]*4+0)*LDP + wk[u]] = wh; WsL[(wn[u]*4+0)*LDP + wk[u]] = wl;
            split_tf32(wv[u].y, wh, wl); WsH[(wn[u]*4+1)*LDP + wk[u]] = wh; WsL[(wn[u]*4+1)*LDP + wk[u]] = wl;
            split_tf32(wv[u].z, wh, wl); WsH[(wn[u]*4+2)*LDP + wk[u]] = wh; WsL[(wn[u]*4+2)*LDP + wk[u]] = wl;
            split_tf32(wv[u].w, wh, wl); WsH[(wn[u]*4+3)*LDP + wk[u]] = wh; WsL[(wn[u]*4+3)*LDP + wk[u]] = wl;
        }
        __syncthreads();

        #pragma unroll
        for (int ks = 0; ks < 2; ks++) {
            int k0 = ks * 8;
            float bh[4][2], bl[4][2];
            #pragma unroll
            for (int ni = 0; ni < 4; ni++) {
                int n = (warpN * 32 + ni * 8 + grp) * LDP + k0 + th4;
                bh[ni][0] = WsH[n];     bh[ni][1] = WsH[n + 4];
                bl[ni][0] = WsL[n];     bl[ni][1] = WsL[n + 4];
            }
            #pragma unroll
            for (int mi = 0; mi < 4; mi++) {
                int m = (warpM * 64 + mi * 16 + grp) * LDP + k0 + th4;
                float ah0 = AsH[m],           ah2 = AsH[m + 4];
                float ah1 = AsH[m + 8 * LDP], ah3 = AsH[m + 8 * LDP + 4];
                float al0 = AsL[m],           al2 = AsL[m + 4];
                float al1 = AsL[m + 8 * LDP], al3 = AsL[m + 8 * LDP + 4];
                #pragma unroll
                for (int ni = 0; ni < 4; ni++) {
                    mma_tf32(c[mi][ni], ah0, ah1, ah2, ah3, bh[ni][0], bh[ni][1]);
                    mma_tf32(c[mi][ni], ah0, ah1, ah2, ah3, bl[ni][0], bl[ni][1]);
                    mma_tf32(c[mi][ni], al0, al1, al2, al3, bh[ni][0], bh[ni][1]);
                }
            }
        }
    }

    float ss[4][2], qq[4][2];
    #pragma unroll
    for (int ni = 0; ni < 4; ni++) { ss[ni][0]=ss[ni][1]=qq[ni][0]=qq[ni][1]=0.f; }

    #pragma unroll
    for (int ni = 0; ni < 4; ni++) {
        int col = warpN * 32 + ni * 8 + 2 * th4;
        float b0 = __ldg(bias + col), b1 = __ldg(bias + col + 1);
        #pragma unroll
        for (int mi = 0; mi < 4; mi++) {
            int rlo = row0 + warpM * 64 + mi * 16 + grp;
            if (rlo < N) {
                float v0 = c[mi][ni][0] + b0;
                float v1 = c[mi][ni][1] + b1;
                *reinterpret_cast<float2*>(out + (size_t)rlo * D + col) = make_float2(v0, v1);
                ss[ni][0] += v0; qq[ni][0] += v0 * v0;
                ss[ni][1] += v1; qq[ni][1] += v1 * v1;
            }
            int rhi = rlo + 8;
            if (rhi < N) {
                float v2 = c[mi][ni][2] + b0;
                float v3 = c[mi][ni][3] + b1;
                *reinterpret_cast<float2*>(out + (size_t)rhi * D + col) = make_float2(v2, v3);
                ss[ni][0] += v2; qq[ni][0] += v2 * v2;
                ss[ni][1] += v3; qq[ni][1] += v3 * v3;
            }
        }
    }
    #pragma unroll
    for (int ni = 0; ni < 4; ni++)
        #pragma unroll
        for (int j = 0; j < 2; j++) {
            float s = ss[ni][j], q = qq[ni][j];
            #pragma unroll
            for (int off = 4; off < 32; off <<= 1) {
                s += __shfl_xor_sync(0xffffffffu, s, off);
                q += __shfl_xor_sync(0xffffffffu, q, off);
            }
            if (lane < 4) {
                int col = warpN * 32 + ni * 8 + 2 * lane + j;
                atomicAdd(&scol[col],  s);
                atomicAdd(&scolq[col], q);
            }
        }
    __syncthreads();
    if (tid < D) {
        atomicAdd(&g_colsum[tid], scol[tid]);
        atomicAdd(&g_colsq[tid],  scolq[tid]);
    }
}

// ---------------- K5: BN finalize + relu + residual -----------------------------
__global__ void k_bn(const float* __restrict__ x, const float* __restrict__ gamma,
                     const float* __restrict__ beta, float* __restrict__ out, int N) {
    __shared__ float ssc[D], ssh[D];
    int t = threadIdx.x;
    if (t < D) {
        float invN = 1.f / (float)N;
        float mean = g_colsum[t] * invN;
        float var  = g_colsq[t] * invN - mean * mean;
        float sc = gamma[t] * rsqrtf(var + 1e-5f);
        ssc[t] = sc;
        ssh[t] = beta[t] - mean * sc;
    }
    __syncthreads();
    int i = blockIdx.x * blockDim.x + t;
    int tot = N * (D / 4);
    if (i < tot) {
        int c = (i & 31) * 4;
        float4 o  = reinterpret_cast<float4*>(out)[i];
        float4 xr = reinterpret_cast<const float4*>(x)[i];
        o.x = fmaxf(fmaf(o.x, ssc[c + 0], ssh[c + 0]), 0.f) + xr.x;
        o.y = fmaxf(fmaf(o.y, ssc[c + 1], ssh[c + 1]), 0.f) + xr.y;
        o.z = fmaxf(fmaf(o.z, ssc[c + 2], ssh[c + 2]), 0.f) + xr.z;
        o.w = fmaxf(fmaf(o.w, ssc[c + 3], ssh[c + 3]), 0.f) + xr.w;
        reinterpret_cast<float4*>(out)[i] = o;
    }
}

// ---------------- launch --------------------------------------------------------
extern "C" void kernel_launch(void* const* d_in, const int* in_sizes, int n_in,
                              void* d_out, int out_size) {
    const float* x     = (const float*)d_in[0];
    const void*  ei    = d_in[1];
    const float* ew    = (const float*)d_in[2];
    const float* pw1   = (const float*)d_in[3];
    const float* pw2   = (const float*)d_in[4];
    const float* sw    = (const float*)d_in[5];
    const float* sb    = (const float*)d_in[6];
    const float* gamma = (const float*)d_in[7];
    const float* beta  = (const float*)d_in[8];
    float* out = (float*)d_out;

    int N = in_sizes[0] / D;
    int E = in_sizes[1] / 2;

    k_detect<<<1, 32>>>((const int*)ei);
    k_zero<<<4096, 256>>>(N);
    k_bounds<<<1, 256>>>(pw1);
    k_sectors<<<SECT, D>>>(pw1, pw2);
    k_prep<<<1024, 256>>>(ei, ew, E);
    k_edges<<<dim3(256, NQ), 256>>>(x, ew, E);
    k_gemm<<<(N + 127) / 128, 256>>>(x, sw, sb, out, N);
    k_bn<<<(N * (D / 4) + 255) / 256, 256>>>(x, gamma, beta, out, N);
}

// round 9
// speedup vs baseline: 1.1375x; 1.1375x over previous
#include <cuda_runtime.h>
#include <math.h>
#include <stdint.h>

#define D 128
#define NMAX 100000
#define SECT 256

#define PI_F      3.14159265358979f
#define HALFPI_F  1.57079632679490f
#define TWOPI_F   6.28318530717959f

// ---------------- scratch (static device globals; no runtime alloc) ------------
__device__ float g_acc[(size_t)NMAX * D];   // 51.2 MB scatter accumulator
__device__ float g_cnt[NMAX];               // per-dst edge counts
__device__ float g_bounds[SECT];            // sorted sector boundary angles
__device__ float g_U[SECT * D];             // sector tables: pe = w0*U[s] + w1*V[s]
__device__ float g_V[SECT * D];
__device__ float g_colsum[D];               // BN stats
__device__ float g_colsq[D];
__device__ int   g_ei64;                    // 1 if edge_index is int64

// ---------------- K-1: detect edge_index dtype ---------------------------------
__global__ void k_detect(const int* __restrict__ w) {
    if (threadIdx.x == 0 && blockIdx.x == 0) {
        int all0 = 1;
        #pragma unroll
        for (int j = 1; j < 64; j += 2) all0 &= (w[j] == 0);
        g_ei64 = all0;
    }
}

// ---------------- K0: zero scratch ---------------------------------------------
__global__ void k_zero(int n) {
    int nd4 = n * (D / 4);
    float4 z = make_float4(0.f, 0.f, 0.f, 0.f);
    int stride = gridDim.x * blockDim.x;
    for (int i = blockIdx.x * blockDim.x + threadIdx.x; i < nd4; i += stride)
        reinterpret_cast<float4*>(g_acc)[i] = z;
    for (int i = blockIdx.x * blockDim.x + threadIdx.x; i < n; i += stride)
        g_cnt[i] = 0.f;
    if (blockIdx.x == 0 && threadIdx.x < D) {
        g_colsum[threadIdx.x] = 0.f;
        g_colsq[threadIdx.x]  = 0.f;
    }
}

// ---------------- K1: bounds + sector tables (merged; 256 blocks x 256 thr) -----
// Every block redundantly computes + rank-sorts the 256 boundary angles (cheap,
// fully parallel), then block s builds U[s], V[s] with the u/v dot products
// split across the two thread halves.
__global__ __launch_bounds__(256) void k_sectors(const float* __restrict__ pw1,
                                                 const float* __restrict__ pw2) {
    __shared__ float raw[SECT];
    __shared__ float sb[SECT];
    __shared__ float Am[D], Bm[D];
    int t = threadIdx.x;
    if (t < D) {
        float A = pw1[t];
        float B = pw1[D + t];
        float phi = atan2f(B, A);
        float c0 = phi + HALFPI_F; if (c0 >  PI_F) c0 -= TWOPI_F;
        float c1 = phi - HALFPI_F; if (c1 < -PI_F) c1 += TWOPI_F;
        raw[2 * t]     = c0;
        raw[2 * t + 1] = c1;
    }
    __syncthreads();
    float v = raw[t];
    int rank = 0;
    #pragma unroll 8
    for (int j = 0; j < SECT; j++) {
        float u = raw[j];
        rank += (u < v) || (u == v && j < t);
    }
    sb[rank] = v;
    if (blockIdx.x == 0) g_bounds[rank] = v;   // k_edges reads after this kernel
    __syncthreads();

    int s = blockIdx.x;
    float b0 = sb[s];
    float b1 = (s < SECT - 1) ? sb[s + 1] : (sb[0] + TWOPI_F);
    float thc = 0.5f * (b0 + b1);
    float c = cosf(thc), sn = sinf(thc);
    if (t < D) {
        float A = pw1[t], B = pw1[D + t];
        bool m = fmaf(A, c, B * sn) > 0.f;
        Am[t] = m ? A : 0.f;
        Bm[t] = m ? B : 0.f;
    }
    __syncthreads();
    // threads [0,128): u for col k; threads [128,256): v for col k
    int k = t & (D - 1);
    bool dov = t >= D;
    float acc = 0.f;
    #pragma unroll 8
    for (int d = 0; d < D; d++) {
        float w = pw2[d * D + k];
        acc = fmaf(dov ? Bm[d] : Am[d], w, acc);
    }
    if (dov) g_V[s * D + k] = acc;
    else     g_U[s * D + k] = acc;
}

// ---------------- K3: edges — batched metadata + warp-per-edge vector phase -----
__global__ __launch_bounds__(256) void k_edges(const float* __restrict__ x,
                                               const void* __restrict__ ei_raw,
                                               const float* __restrict__ ew, int E) {
    __shared__ float sbound[SECT];
    int t = threadIdx.x;
    sbound[t] = g_bounds[t];
    __syncthreads();
    const long long* ei64 = (const long long*)ei_raw;
    const int*       ei32 = (const int*)ei_raw;
    int is64 = g_ei64;
    int lane = t & 31;
    int wid  = blockIdx.x * 8 + (t >> 5);
    int stride = gridDim.x * 8 * 32;

    for (int e0 = wid * 32; e0 < E; e0 += stride) {
        int e = e0 + lane;
        int src = 0, dst = 0, sct = 0;
        float w0 = 0.f, w1 = 0.f;
        if (e < E) {
            if (is64) { src = (int)ei64[e]; dst = (int)ei64[E + e]; }
            else      { src = ei32[e];      dst = ei32[E + e]; }
            float2 wv = reinterpret_cast<const float2*>(ew)[e];
            w0 = wv.x; w1 = wv.y;
            float th = atan2f(w1, w0);
            int lo = 0, hi = SECT;
            while (lo < hi) {
                int mid = (lo + hi) >> 1;
                if (sbound[mid] <= th) lo = mid + 1; else hi = mid;
            }
            sct = (lo == 0) ? (SECT - 1) : (lo - 1);
            atomicAdd(&g_cnt[dst], 1.f);
        }

        #define EDGE_BODY(i)                                                          \
        {                                                                             \
            int   s_  = __shfl_sync(0xffffffffu, src, (i));                           \
            int   dd_ = __shfl_sync(0xffffffffu, dst, (i));                           \
            int   sc_ = __shfl_sync(0xffffffffu, sct, (i));                           \
            float a0_ = __shfl_sync(0xffffffffu, w0, (i));                            \
            float a1_ = __shfl_sync(0xffffffffu, w1, (i));                            \
            float4 xj = __ldg(reinterpret_cast<const float4*>(x + (size_t)s_ * D) + lane); \
            float4 u4 = __ldg(reinterpret_cast<const float4*>(g_U + sc_ * D) + lane); \
            float4 v4 = __ldg(reinterpret_cast<const float4*>(g_V + sc_ * D) + lane); \
            float4 m;                                                                 \
            m.x = xj.x * fmaf(a0_, u4.x, fmaf(a1_, v4.x, 1.f));                       \
            m.y = xj.y * fmaf(a0_, u4.y, fmaf(a1_, v4.y, 1.f));                       \
            m.z = xj.z * fmaf(a0_, u4.z, fmaf(a1_, v4.z, 1.f));                       \
            m.w = xj.w * fmaf(a0_, u4.w, fmaf(a1_, v4.w, 1.f));                       \
            float* p = g_acc + (size_t)dd_ * D + lane * 4;                            \
            asm volatile("red.global.add.v4.f32 [%0], {%1, %2, %3, %4};"              \
                         :: "l"(p), "f"(m.x), "f"(m.y), "f"(m.z), "f"(m.w) : "memory"); \
        }

        int cnt = E - e0; if (cnt > 32) cnt = 32;
        if (cnt == 32) {
            #pragma unroll 4
            for (int i = 0; i < 32; i++) EDGE_BODY(i)
        } else {
            for (int i = 0; i < cnt; i++) EDGE_BODY(i)
        }
        #undef EDGE_BODY
    }
}

// ---------------- tf32 helpers --------------------------------------------------
__device__ __forceinline__ void split_tf32(float a, float& hi, float& lo) {
    unsigned hb, lb;
    asm("cvt.rna.tf32.f32 %0, %1;" : "=r"(hb) : "f"(a));
    hi = __uint_as_float(hb);
    float r = a - hi;
    asm("cvt.rna.tf32.f32 %0, %1;" : "=r"(lb) : "f"(r));
    lo = __uint_as_float(lb);
}

__device__ __forceinline__ void mma_tf32(float* d, float a0, float a1, float a2, float a3,
                                         float b0, float b1) {
    asm volatile(
        "mma.sync.aligned.m16n8k8.row.col.f32.tf32.tf32.f32 "
        "{%0,%1,%2,%3}, {%4,%5,%6,%7}, {%8,%9}, {%0,%1,%2,%3};\n"
        : "+f"(d[0]), "+f"(d[1]), "+f"(d[2]), "+f"(d[3])
        : "r"(__float_as_uint(a0)), "r"(__float_as_uint(a1)),
          "r"(__float_as_uint(a2)), "r"(__float_as_uint(a3)),
          "r"(__float_as_uint(b0)), "r"(__float_as_uint(b1)));
}

// ---------------- K4: tensor-core GEMM [N,256]@[256,128], 3xTF32 ----------------
#define LDP 20
__global__ __launch_bounds__(256, 2) void k_gemm(const float* __restrict__ x,
                                                 const float* __restrict__ W,
                                                 const float* __restrict__ bias,
                                                 float* __restrict__ out, int N) {
    __shared__ float AsH[128 * LDP], AsL[128 * LDP];
    __shared__ float WsH[128 * LDP], WsL[128 * LDP];
    __shared__ float inv_s[128];
    __shared__ float scol[128], scolq[128];

    int tid = threadIdx.x;
    int row0 = blockIdx.x * 128;
    if (tid < 128) {
        int r = row0 + tid;
        inv_s[tid] = (r < N) ? (1.f / fmaxf(g_cnt[r], 1.f)) : 0.f;
        scol[tid] = 0.f; scolq[tid] = 0.f;
    }

    int lane  = tid & 31;
    int warp  = tid >> 5;
    int warpM = warp >> 2;
    int warpN = warp & 3;
    int grp   = lane >> 2;
    int th4   = lane & 3;

    float c[4][4][4];
    #pragma unroll
    for (int mi = 0; mi < 4; mi++)
        #pragma unroll
        for (int ni = 0; ni < 4; ni++)
            #pragma unroll
            for (int j = 0; j < 4; j++) c[mi][ni][j] = 0.f;

    __syncthreads();

    for (int kt = 0; kt < 16; kt++) {
        float4 av[2]; float ainv[2]; int am[2];
        float4 wv[2]; int wk[2], wn[2];
        #pragma unroll
        for (int u = 0; u < 2; u++) {
            int s = tid + u * 256;
            int m  = s >> 2, ch = s & 3;
            am[u] = m;
            int r = row0 + m;
            av[u] = make_float4(0.f, 0.f, 0.f, 0.f);
            ainv[u] = 1.f;
            if (r < N) {
                if (kt < 8) {
                    av[u] = *reinterpret_cast<const float4*>(x + (size_t)r * D + kt * 16 + ch * 4);
                } else {
                    av[u] = *reinterpret_cast<const float4*>(g_acc + (size_t)r * D + (kt - 8) * 16 + ch * 4);
                    ainv[u] = inv_s[m];
                }
            }
            int kr = s & 15, n4 = s >> 4;
            wk[u] = kr; wn[u] = n4;
            wv[u] = *reinterpret_cast<const float4*>(W + (size_t)(kt * 16 + kr) * D + n4 * 4);
        }

        __syncthreads();
        #pragma unroll
        for (int u = 0; u < 2; u++) {
            float iv = ainv[u];
            float h0, l0, h1, l1, h2, l2, h3, l3;
            split_tf32(av[u].x * iv, h0, l0);
            split_tf32(av[u].y * iv, h1, l1);
            split_tf32(av[u].z * iv, h2, l2);
            split_tf32(av[u].w * iv, h3, l3);
            int s = tid + u * 256;
            int base = am[u] * LDP + (s & 3) * 4;
            *reinterpret_cast<float4*>(&AsH[base]) = make_float4(h0, h1, h2, h3);
            *reinterpret_cast<float4*>(&AsL[base]) = make_float4(l0, l1, l2, l3);
            float wh, wl;
            split_tf32(wv[u].x, wh, wl); WsH[(wn[u]*4+0)*LDP + wk[u]] = wh; WsL[(wn[u]*4+0)*LDP + wk[u]] = wl;
            split_tf32(wv[u].y, wh, wl); WsH[(wn[u]*4+1)*LDP + wk[u]] = wh; WsL[(wn[u]*4+1)*LDP + wk[u]] = wl;
            split_tf32(wv[u].z, wh, wl); WsH[(wn[u]*4+2)*LDP + wk[u]] = wh; WsL[(wn[u]*4+2)*LDP + wk[u]] = wl;
            split_tf32(wv[u].w, wh, wl); WsH[(wn[u]*4+3)*LDP + wk[u]] = wh; WsL[(wn[u]*4+3)*LDP + wk[u]] = wl;
        }
        __syncthreads();

        #pragma unroll
        for (int ks = 0; ks < 2; ks++) {
            int k0 = ks * 8;
            float bh[4][2], bl[4][2];
            #pragma unroll
            for (int ni = 0; ni < 4; ni++) {
                int n = (warpN * 32 + ni * 8 + grp) * LDP + k0 + th4;
                bh[ni][0] = WsH[n];     bh[ni][1] = WsH[n + 4];
                bl[ni][0] = WsL[n];     bl[ni][1] = WsL[n + 4];
            }
            #pragma unroll
            for (int mi = 0; mi < 4; mi++) {
                int m = (warpM * 64 + mi * 16 + grp) * LDP + k0 + th4;
                float ah0 = AsH[m],           ah2 = AsH[m + 4];
                float ah1 = AsH[m + 8 * LDP], ah3 = AsH[m + 8 * LDP + 4];
                float al0 = AsL[m],           al2 = AsL[m + 4];
                float al1 = AsL[m + 8 * LDP], al3 = AsL[m + 8 * LDP + 4];
                #pragma unroll
                for (int ni = 0; ni < 4; ni++) {
                    mma_tf32(c[mi][ni], ah0, ah1, ah2, ah3, bh[ni][0], bh[ni][1]);
                    mma_tf32(c[mi][ni], ah0, ah1, ah2, ah3, bl[ni][0], bl[ni][1]);
                    mma_tf32(c[mi][ni], al0, al1, al2, al3, bh[ni][0], bh[ni][1]);
                }
            }
        }
    }

    float ss[4][2], qq[4][2];
    #pragma unroll
    for (int ni = 0; ni < 4; ni++) { ss[ni][0]=ss[ni][1]=qq[ni][0]=qq[ni][1]=0.f; }

    #pragma unroll
    for (int ni = 0; ni < 4; ni++) {
        int col = warpN * 32 + ni * 8 + 2 * th4;
        float b0 = __ldg(bias + col), b1 = __ldg(bias + col + 1);
        #pragma unroll
        for (int mi = 0; mi < 4; mi++) {
            int rlo = row0 + warpM * 64 + mi * 16 + grp;
            if (rlo < N) {
                float v0 = c[mi][ni][0] + b0;
                float v1 = c[mi][ni][1] + b1;
                *reinterpret_cast<float2*>(out + (size_t)rlo * D + col) = make_float2(v0, v1);
                ss[ni][0] += v0; qq[ni][0] += v0 * v0;
                ss[ni][1] += v1; qq[ni][1] += v1 * v1;
            }
            int rhi = rlo + 8;
            if (rhi < N) {
                float v2 = c[mi][ni][2] + b0;
                float v3 = c[mi][ni][3] + b1;
                *reinterpret_cast<float2*>(out + (size_t)rhi * D + col) = make_float2(v2, v3);
                ss[ni][0] += v2; qq[ni][0] += v2 * v2;
                ss[ni][1] += v3; qq[ni][1] += v3 * v3;
            }
        }
    }
    #pragma unroll
    for (int ni = 0; ni < 4; ni++)
        #pragma unroll
        for (int j = 0; j < 2; j++) {
            float s = ss[ni][j], q = qq[ni][j];
            #pragma unroll
            for (int off = 4; off < 32; off <<= 1) {
                s += __shfl_xor_sync(0xffffffffu, s, off);
                q += __shfl_xor_sync(0xffffffffu, q, off);
            }
            if (lane < 4) {
                int col = warpN * 32 + ni * 8 + 2 * lane + j;
                atomicAdd(&scol[col],  s);
                atomicAdd(&scolq[col], q);
            }
        }
    __syncthreads();
    if (tid < D) {
        atomicAdd(&g_colsum[tid], scol[tid]);
        atomicAdd(&g_colsq[tid],  scolq[tid]);
    }
}

// ---------------- K5: BN finalize + relu + residual -----------------------------
__global__ void k_bn(const float* __restrict__ x, const float* __restrict__ gamma,
                     const float* __restrict__ beta, float* __restrict__ out, int N) {
    __shared__ float ssc[D], ssh[D];
    int t = threadIdx.x;
    if (t < D) {
        float invN = 1.f / (float)N;
        float mean = g_colsum[t] * invN;
        float var  = g_colsq[t] * invN - mean * mean;
        float sc = gamma[t] * rsqrtf(var + 1e-5f);
        ssc[t] = sc;
        ssh[t] = beta[t] - mean * sc;
    }
    __syncthreads();
    int i = blockIdx.x * blockDim.x + t;
    int tot = N * (D / 4);
    if (i < tot) {
        int c = (i & 31) * 4;
        float4 o  = reinterpret_cast<float4*>(out)[i];
        float4 xr = reinterpret_cast<const float4*>(x)[i];
        o.x = fmaxf(fmaf(o.x, ssc[c + 0], ssh[c + 0]), 0.f) + xr.x;
        o.y = fmaxf(fmaf(o.y, ssc[c + 1], ssh[c + 1]), 0.f) + xr.y;
        o.z = fmaxf(fmaf(o.z, ssc[c + 2], ssh[c + 2]), 0.f) + xr.z;
        o.w = fmaxf(fmaf(o.w, ssc[c + 3], ssh[c + 3]), 0.f) + xr.w;
        reinterpret_cast<float4*>(out)[i] = o;
    }
}

// ---------------- launch --------------------------------------------------------
extern "C" void kernel_launch(void* const* d_in, const int* in_sizes, int n_in,
                              void* d_out, int out_size) {
    const float* x     = (const float*)d_in[0];
    const void*  ei    = d_in[1];
    const float* ew    = (const float*)d_in[2];
    const float* pw1   = (const float*)d_in[3];
    const float* pw2   = (const float*)d_in[4];
    const float* sw    = (const float*)d_in[5];
    const float* sb    = (const float*)d_in[6];
    const float* gamma = (const float*)d_in[7];
    const float* beta  = (const float*)d_in[8];
    float* out = (float*)d_out;

    int N = in_sizes[0] / D;
    int E = in_sizes[1] / 2;

    k_detect<<<1, 32>>>((const int*)ei);
    k_zero<<<4096, 256>>>(N);
    k_sectors<<<SECT, 256>>>(pw1, pw2);
    k_edges<<<4096, 256>>>(x, ei, ew, E);
    k_gemm<<<(N + 127) / 128, 256>>>(x, sw, sb, out, N);
    k_bn<<<(N * (D / 4) + 255) / 256, 256>>>(x, gamma, beta, out, N);
}

// round 10
// speedup vs baseline: 1.1446x; 1.0063x over previous
#include <cuda_runtime.h>
#include <cuda_bf16.h>
#include <math.h>
#include <stdint.h>

#define D 128
#define NMAX 100000
#define SECT 256

#define PI_F      3.14159265358979f
#define HALFPI_F  1.57079632679490f
#define TWOPI_F   6.28318530717959f

// ---------------- scratch (static device globals; no runtime alloc) ------------
__device__ float g_acc[(size_t)NMAX * D];   // 51.2 MB scatter accumulator
__device__ float g_cnt[NMAX];               // per-dst edge counts
__device__ float g_bounds[SECT];            // sorted sector boundary angles
__device__ float g_U[SECT * D];             // sector tables: pe = w0*U[s] + w1*V[s]
__device__ float g_V[SECT * D];
__device__ float g_colsum[D];               // BN stats
__device__ float g_colsq[D];
__device__ int   g_ei64;                    // 1 if edge_index is int64

// ---------------- K0: zero scratch + edge-index dtype detect --------------------
__global__ void k_zero(const int* __restrict__ w, int n) {
    if (blockIdx.x == 0 && threadIdx.x == 0) {
        int all0 = 1;
        #pragma unroll
        for (int j = 1; j < 64; j += 2) all0 &= (w[j] == 0);
        g_ei64 = all0;
    }
    int nd4 = n * (D / 4);
    float4 z = make_float4(0.f, 0.f, 0.f, 0.f);
    int stride = gridDim.x * blockDim.x;
    for (int i = blockIdx.x * blockDim.x + threadIdx.x; i < nd4; i += stride)
        reinterpret_cast<float4*>(g_acc)[i] = z;
    for (int i = blockIdx.x * blockDim.x + threadIdx.x; i < n; i += stride)
        g_cnt[i] = 0.f;
    if (blockIdx.x == 0 && threadIdx.x < D) {
        g_colsum[threadIdx.x] = 0.f;
        g_colsq[threadIdx.x]  = 0.f;
    }
}

// ---------------- K1: bounds + sector tables (merged; 256 blocks x 256 thr) -----
__global__ __launch_bounds__(256) void k_sectors(const float* __restrict__ pw1,
                                                 const float* __restrict__ pw2) {
    __shared__ float raw[SECT];
    __shared__ float sb[SECT];
    __shared__ float Am[D], Bm[D];
    int t = threadIdx.x;
    if (t < D) {
        float A = pw1[t];
        float B = pw1[D + t];
        float phi = atan2f(B, A);
        float c0 = phi + HALFPI_F; if (c0 >  PI_F) c0 -= TWOPI_F;
        float c1 = phi - HALFPI_F; if (c1 < -PI_F) c1 += TWOPI_F;
        raw[2 * t]     = c0;
        raw[2 * t + 1] = c1;
    }
    __syncthreads();
    float v = raw[t];
    int rank = 0;
    #pragma unroll 8
    for (int j = 0; j < SECT; j++) {
        float u = raw[j];
        rank += (u < v) || (u == v && j < t);
    }
    sb[rank] = v;
    if (blockIdx.x == 0) g_bounds[rank] = v;
    __syncthreads();

    int s = blockIdx.x;
    float b0 = sb[s];
    float b1 = (s < SECT - 1) ? sb[s + 1] : (sb[0] + TWOPI_F);
    float thc = 0.5f * (b0 + b1);
    float c = cosf(thc), sn = sinf(thc);
    if (t < D) {
        float A = pw1[t], B = pw1[D + t];
        bool m = fmaf(A, c, B * sn) > 0.f;
        Am[t] = m ? A : 0.f;
        Bm[t] = m ? B : 0.f;
    }
    __syncthreads();
    int k = t & (D - 1);
    bool dov = t >= D;
    float acc = 0.f;
    #pragma unroll 8
    for (int d = 0; d < D; d++) {
        float w = pw2[d * D + k];
        acc = fmaf(dov ? Bm[d] : Am[d], w, acc);
    }
    if (dov) g_V[s * D + k] = acc;
    else     g_U[s * D + k] = acc;
}

// ---------------- K3: edges — batched metadata + warp-per-edge vector phase -----
__global__ __launch_bounds__(256) void k_edges(const float* __restrict__ x,
                                               const void* __restrict__ ei_raw,
                                               const float* __restrict__ ew, int E) {
    __shared__ float sbound[SECT];
    int t = threadIdx.x;
    sbound[t] = g_bounds[t];
    __syncthreads();
    const long long* ei64 = (const long long*)ei_raw;
    const int*       ei32 = (const int*)ei_raw;
    int is64 = g_ei64;
    int lane = t & 31;
    int wid  = blockIdx.x * 8 + (t >> 5);
    int stride = gridDim.x * 8 * 32;

    for (int e0 = wid * 32; e0 < E; e0 += stride) {
        int e = e0 + lane;
        int src = 0, dst = 0, sct = 0;
        float w0 = 0.f, w1 = 0.f;
        if (e < E) {
            if (is64) { src = (int)ei64[e]; dst = (int)ei64[E + e]; }
            else      { src = ei32[e];      dst = ei32[E + e]; }
            float2 wv = reinterpret_cast<const float2*>(ew)[e];
            w0 = wv.x; w1 = wv.y;
            float th = atan2f(w1, w0);
            int lo = 0, hi = SECT;
            while (lo < hi) {
                int mid = (lo + hi) >> 1;
                if (sbound[mid] <= th) lo = mid + 1; else hi = mid;
            }
            sct = (lo == 0) ? (SECT - 1) : (lo - 1);
            atomicAdd(&g_cnt[dst], 1.f);
        }

        #define EDGE_BODY(i)                                                          \
        {                                                                             \
            int   s_  = __shfl_sync(0xffffffffu, src, (i));                           \
            int   dd_ = __shfl_sync(0xffffffffu, dst, (i));                           \
            int   sc_ = __shfl_sync(0xffffffffu, sct, (i));                           \
            float a0_ = __shfl_sync(0xffffffffu, w0, (i));                            \
            float a1_ = __shfl_sync(0xffffffffu, w1, (i));                            \
            float4 xj = __ldg(reinterpret_cast<const float4*>(x + (size_t)s_ * D) + lane); \
            float4 u4 = __ldg(reinterpret_cast<const float4*>(g_U + sc_ * D) + lane); \
            float4 v4 = __ldg(reinterpret_cast<const float4*>(g_V + sc_ * D) + lane); \
            float4 m;                                                                 \
            m.x = xj.x * fmaf(a0_, u4.x, fmaf(a1_, v4.x, 1.f));                       \
            m.y = xj.y * fmaf(a0_, u4.y, fmaf(a1_, v4.y, 1.f));                       \
            m.z = xj.z * fmaf(a0_, u4.z, fmaf(a1_, v4.z, 1.f));                       \
            m.w = xj.w * fmaf(a0_, u4.w, fmaf(a1_, v4.w, 1.f));                       \
            float* p = g_acc + (size_t)dd_ * D + lane * 4;                            \
            asm volatile("red.global.add.v4.f32 [%0], {%1, %2, %3, %4};"              \
                         :: "l"(p), "f"(m.x), "f"(m.y), "f"(m.z), "f"(m.w) : "memory"); \
        }

        int cnt = E - e0; if (cnt > 32) cnt = 32;
        if (cnt == 32) {
            #pragma unroll 4
            for (int i = 0; i < 32; i++) EDGE_BODY(i)
        } else {
            for (int i = 0; i < cnt; i++) EDGE_BODY(i)
        }
        #undef EDGE_BODY
    }
}

// ---------------- bf16 helpers --------------------------------------------------
// hi = exactly-bf16-representable part (stored as f32); lo = residual (rounded to
// bf16 only at pack time). 3-pass product keeps hi*hi + hi*lo + lo*hi; dropped
// lo*lo ~ 2^-18 relative.
__device__ __forceinline__ void split_bf16(float a, float& hi, float& lo) {
    hi = __bfloat162float(__float2bfloat16_rn(a));
    lo = a - hi;
}

// pack two f32 (k-even, k-odd) into bf16x2 register: low half = even, high = odd
__device__ __forceinline__ unsigned pack_bf16(float even, float odd) {
    unsigned r;
    asm("cvt.rn.bf16x2.f32 %0, %1, %2;" : "=r"(r) : "f"(odd), "f"(even));
    return r;
}

__device__ __forceinline__ void mma_bf16(float* d, unsigned a0, unsigned a1,
                                         unsigned a2, unsigned a3,
                                         unsigned b0, unsigned b1) {
    asm volatile(
        "mma.sync.aligned.m16n8k16.row.col.f32.bf16.bf16.f32 "
        "{%0,%1,%2,%3}, {%4,%5,%6,%7}, {%8,%9}, {%0,%1,%2,%3};\n"
        : "+f"(d[0]), "+f"(d[1]), "+f"(d[2]), "+f"(d[3])
        : "r"(a0), "r"(a1), "r"(a2), "r"(a3), "r"(b0), "r"(b1));
}

// ---------------- K4: tensor-core GEMM [N,256]@[256,128], 3x bf16-split ---------
// Block: 128 rows x 128 cols, 256 threads = 8 warps (2 M x 4 N), warp tile 64x32.
// m16n8k16 covers the whole BK=16 slice in one k-step; 48 mma/thread/kt.
#define LDP 20
__global__ __launch_bounds__(256, 2) void k_gemm(const float* __restrict__ x,
                                                 const float* __restrict__ W,
                                                 const float* __restrict__ bias,
                                                 float* __restrict__ out, int N) {
    __shared__ float AsH[128 * LDP], AsL[128 * LDP];
    __shared__ float WsH[128 * LDP], WsL[128 * LDP];
    __shared__ float inv_s[128];
    __shared__ float scol[128], scolq[128];

    int tid = threadIdx.x;
    int row0 = blockIdx.x * 128;
    if (tid < 128) {
        int r = row0 + tid;
        inv_s[tid] = (r < N) ? (1.f / fmaxf(g_cnt[r], 1.f)) : 0.f;
        scol[tid] = 0.f; scolq[tid] = 0.f;
    }

    int lane  = tid & 31;
    int warp  = tid >> 5;
    int warpM = warp >> 2;
    int warpN = warp & 3;
    int grp   = lane >> 2;
    int th4   = lane & 3;

    float c[4][4][4];
    #pragma unroll
    for (int mi = 0; mi < 4; mi++)
        #pragma unroll
        for (int ni = 0; ni < 4; ni++)
            #pragma unroll
            for (int j = 0; j < 4; j++) c[mi][ni][j] = 0.f;

    __syncthreads();

    for (int kt = 0; kt < 16; kt++) {
        float4 av[2]; float ainv[2]; int am[2];
        float4 wv[2]; int wk[2], wn[2];
        #pragma unroll
        for (int u = 0; u < 2; u++) {
            int s = tid + u * 256;
            int m  = s >> 2, ch = s & 3;
            am[u] = m;
            int r = row0 + m;
            av[u] = make_float4(0.f, 0.f, 0.f, 0.f);
            ainv[u] = 1.f;
            if (r < N) {
                if (kt < 8) {
                    av[u] = *reinterpret_cast<const float4*>(x + (size_t)r * D + kt * 16 + ch * 4);
                } else {
                    av[u] = *reinterpret_cast<const float4*>(g_acc + (size_t)r * D + (kt - 8) * 16 + ch * 4);
                    ainv[u] = inv_s[m];
                }
            }
            int kr = s & 15, n4 = s >> 4;
            wk[u] = kr; wn[u] = n4;
            wv[u] = *reinterpret_cast<const float4*>(W + (size_t)(kt * 16 + kr) * D + n4 * 4);
        }

        __syncthreads();
        #pragma unroll
        for (int u = 0; u < 2; u++) {
            float iv = ainv[u];
            float h0, l0, h1, l1, h2, l2, h3, l3;
            split_bf16(av[u].x * iv, h0, l0);
            split_bf16(av[u].y * iv, h1, l1);
            split_bf16(av[u].z * iv, h2, l2);
            split_bf16(av[u].w * iv, h3, l3);
            int s = tid + u * 256;
            int base = am[u] * LDP + (s & 3) * 4;
            *reinterpret_cast<float4*>(&AsH[base]) = make_float4(h0, h1, h2, h3);
            *reinterpret_cast<float4*>(&AsL[base]) = make_float4(l0, l1, l2, l3);
            float wh, wl;
            split_bf16(wv[u].x, wh, wl); WsH[(wn[u]*4+0)*LDP + wk[u]] = wh; WsL[(wn[u]*4+0)*LDP + wk[u]] = wl;
            split_bf16(wv[u].y, wh, wl); WsH[(wn[u]*4+1)*LDP + wk[u]] = wh; WsL[(wn[u]*4+1)*LDP + wk[u]] = wl;
            split_bf16(wv[u].z, wh, wl); WsH[(wn[u]*4+2)*LDP + wk[u]] = wh; WsL[(wn[u]*4+2)*LDP + wk[u]] = wl;
            split_bf16(wv[u].w, wh, wl); WsH[(wn[u]*4+3)*LDP + wk[u]] = wh; WsL[(wn[u]*4+3)*LDP + wk[u]] = wl;
        }
        __syncthreads();

        // one m16n8k16 k-step covers the whole 16-deep slice
        unsigned bH[4][2], bL[4][2];
        #pragma unroll
        for (int ni = 0; ni < 4; ni++) {
            int nb = (warpN * 32 + ni * 8 + grp) * LDP + 2 * th4;
            bH[ni][0] = pack_bf16(WsH[nb],     WsH[nb + 1]);
            bH[ni][1] = pack_bf16(WsH[nb + 8], WsH[nb + 9]);
            bL[ni][0] = pack_bf16(WsL[nb],     WsL[nb + 1]);
            bL[ni][1] = pack_bf16(WsL[nb + 8], WsL[nb + 9]);
        }
        #pragma unroll
        for (int mi = 0; mi < 4; mi++) {
            int ar  = (warpM * 64 + mi * 16 + grp) * LDP + 2 * th4;
            int ar8 = ar + 8 * LDP;
            unsigned aH0 = pack_bf16(AsH[ar],      AsH[ar + 1]);
            unsigned aH1 = pack_bf16(AsH[ar8],     AsH[ar8 + 1]);
            unsigned aH2 = pack_bf16(AsH[ar + 8],  AsH[ar + 9]);
            unsigned aH3 = pack_bf16(AsH[ar8 + 8], AsH[ar8 + 9]);
            unsigned aL0 = pack_bf16(AsL[ar],      AsL[ar + 1]);
            unsigned aL1 = pack_bf16(AsL[ar8],     AsL[ar8 + 1]);
            unsigned aL2 = pack_bf16(AsL[ar + 8],  AsL[ar + 9]);
            unsigned aL3 = pack_bf16(AsL[ar8 + 8], AsL[ar8 + 9]);
            #pragma unroll
            for (int ni = 0; ni < 4; ni++) {
                mma_bf16(c[mi][ni], aH0, aH1, aH2, aH3, bH[ni][0], bH[ni][1]);
                mma_bf16(c[mi][ni], aH0, aH1, aH2, aH3, bL[ni][0], bL[ni][1]);
                mma_bf16(c[mi][ni], aL0, aL1, aL2, aL3, bH[ni][0], bH[ni][1]);
            }
        }
    }

    float ss[4][2], qq[4][2];
    #pragma unroll
    for (int ni = 0; ni < 4; ni++) { ss[ni][0]=ss[ni][1]=qq[ni][0]=qq[ni][1]=0.f; }

    #pragma unroll
    for (int ni = 0; ni < 4; ni++) {
        int col = warpN * 32 + ni * 8 + 2 * th4;
        float b0 = __ldg(bias + col), b1 = __ldg(bias + col + 1);
        #pragma unroll
        for (int mi = 0; mi < 4; mi++) {
            int rlo = row0 + warpM * 64 + mi * 16 + grp;
            if (rlo < N) {
                float v0 = c[mi][ni][0] + b0;
                float v1 = c[mi][ni][1] + b1;
                *reinterpret_cast<float2*>(out + (size_t)rlo * D + col) = make_float2(v0, v1);
                ss[ni][0] += v0; qq[ni][0] += v0 * v0;
                ss[ni][1] += v1; qq[ni][1] += v1 * v1;
            }
            int rhi = rlo + 8;
            if (rhi < N) {
                float v2 = c[mi][ni][2] + b0;
                float v3 = c[mi][ni][3] + b1;
                *reinterpret_cast<float2*>(out + (size_t)rhi * D + col) = make_float2(v2, v3);
                ss[ni][0] += v2; qq[ni][0] += v2 * v2;
                ss[ni][1] += v3; qq[ni][1] += v3 * v3;
            }
        }
    }
    #pragma unroll
    for (int ni = 0; ni < 4; ni++)
        #pragma unroll
        for (int j = 0; j < 2; j++) {
            float s = ss[ni][j], q = qq[ni][j];
            #pragma unroll
            for (int off = 4; off < 32; off <<= 1) {
                s += __shfl_xor_sync(0xffffffffu, s, off);
                q += __shfl_xor_sync(0xffffffffu, q, off);
            }
            if (lane < 4) {
                int col = warpN * 32 + ni * 8 + 2 * lane + j;
                atomicAdd(&scol[col],  s);
                atomicAdd(&scolq[col], q);
            }
        }
    __syncthreads();
    if (tid < D) {
        atomicAdd(&g_colsum[tid], scol[tid]);
        atomicAdd(&g_colsq[tid],  scolq[tid]);
    }
}

// ---------------- K5: BN finalize + relu + residual -----------------------------
__global__ void k_bn(const float* __restrict__ x, const float* __restrict__ gamma,
                     const float* __restrict__ beta, float* __restrict__ out, int N) {
    __shared__ float ssc[D], ssh[D];
    int t = threadIdx.x;
    if (t < D) {
        float invN = 1.f / (float)N;
        float mean = g_colsum[t] * invN;
        float var  = g_colsq[t] * invN - mean * mean;
        float sc = gamma[t] * rsqrtf(var + 1e-5f);
        ssc[t] = sc;
        ssh[t] = beta[t] - mean * sc;
    }
    __syncthreads();
    int i = blockIdx.x * blockDim.x + t;
    int tot = N * (D / 4);
    if (i < tot) {
        int c = (i & 31) * 4;
        float4 o  = reinterpret_cast<float4*>(out)[i];
        float4 xr = reinterpret_cast<const float4*>(x)[i];
        o.x = fmaxf(fmaf(o.x, ssc[c + 0], ssh[c + 0]), 0.f) + xr.x;
        o.y = fmaxf(fmaf(o.y, ssc[c + 1], ssh[c + 1]), 0.f) + xr.y;
        o.z = fmaxf(fmaf(o.z, ssc[c + 2], ssh[c + 2]), 0.f) + xr.z;
        o.w = fmaxf(fmaf(o.w, ssc[c + 3], ssh[c + 3]), 0.f) + xr.w;
        reinterpret_cast<float4*>(out)[i] = o;
    }
}

// ---------------- launch --------------------------------------------------------
extern "C" void kernel_launch(void* const* d_in, const int* in_sizes, int n_in,
                              void* d_out, int out_size) {
    const float* x     = (const float*)d_in[0];
    const void*  ei    = d_in[1];
    const float* ew    = (const float*)d_in[2];
    const float* pw1   = (const float*)d_in[3];
    const float* pw2   = (const float*)d_in[4];
    const float* sw    = (const float*)d_in[5];
    const float* sb    = (const float*)d_in[6];
    const float* gamma = (const float*)d_in[7];
    const float* beta  = (const float*)d_in[8];
    float* out = (float*)d_out;

    int N = in_sizes[0] / D;
    int E = in_sizes[1] / 2;

    k_zero<<<4096, 256>>>((const int*)ei, N);
    k_sectors<<<SECT, 256>>>(pw1, pw2);
    k_edges<<<4096, 256>>>(x, ei, ew, E);
    k_gemm<<<(N + 127) / 128, 256>>>(x, sw, sb, out, N);
    k_bn<<<(N * (D / 4) + 255) / 256, 256>>>(x, gamma, beta, out, N);
}

// round 11
// speedup vs baseline: 1.3823x; 1.2077x over previous
#include <cuda_runtime.h>
#include <cuda_bf16.h>
#include <math.h>
#include <stdint.h>

#define D 128
#define NMAX 100000
#define SECT 256

#define PI_F      3.14159265358979f
#define HALFPI_F  1.57079632679490f
#define TWOPI_F   6.28318530717959f

// ---------------- scratch (static device globals; no runtime alloc) ------------
__device__ float g_acc[(size_t)NMAX * D];   // 51.2 MB scatter accumulator
__device__ float g_cnt[NMAX];               // per-dst edge counts
__device__ float g_bounds[SECT];            // sorted sector boundary angles
__device__ float g_U[SECT * D];             // sector tables: pe = w0*U[s] + w1*V[s]
__device__ float g_V[SECT * D];
__device__ float g_colsum[D];               // BN stats
__device__ float g_colsq[D];
__device__ int   g_ei64;                    // 1 if edge_index is int64

// ---------------- K0: zero scratch + edge-index dtype detect --------------------
__global__ void k_zero(const int* __restrict__ w, int n) {
    if (blockIdx.x == 0 && threadIdx.x == 0) {
        int all0 = 1;
        #pragma unroll
        for (int j = 1; j < 64; j += 2) all0 &= (w[j] == 0);
        g_ei64 = all0;
    }
    int nd4 = n * (D / 4);
    float4 z = make_float4(0.f, 0.f, 0.f, 0.f);
    int stride = gridDim.x * blockDim.x;
    for (int i = blockIdx.x * blockDim.x + threadIdx.x; i < nd4; i += stride)
        reinterpret_cast<float4*>(g_acc)[i] = z;
    for (int i = blockIdx.x * blockDim.x + threadIdx.x; i < n; i += stride)
        g_cnt[i] = 0.f;
    if (blockIdx.x == 0 && threadIdx.x < D) {
        g_colsum[threadIdx.x] = 0.f;
        g_colsq[threadIdx.x]  = 0.f;
    }
}

// ---------------- K1: bounds + sector tables (merged; 256 blocks x 256 thr) -----
__global__ __launch_bounds__(256) void k_sectors(const float* __restrict__ pw1,
                                                 const float* __restrict__ pw2) {
    __shared__ float raw[SECT];
    __shared__ float sb[SECT];
    __shared__ float Am[D], Bm[D];
    int t = threadIdx.x;
    if (t < D) {
        float A = pw1[t];
        float B = pw1[D + t];
        float phi = atan2f(B, A);
        float c0 = phi + HALFPI_F; if (c0 >  PI_F) c0 -= TWOPI_F;
        float c1 = phi - HALFPI_F; if (c1 < -PI_F) c1 += TWOPI_F;
        raw[2 * t]     = c0;
        raw[2 * t + 1] = c1;
    }
    __syncthreads();
    float v = raw[t];
    int rank = 0;
    #pragma unroll 8
    for (int j = 0; j < SECT; j++) {
        float u = raw[j];
        rank += (u < v) || (u == v && j < t);
    }
    sb[rank] = v;
    if (blockIdx.x == 0) g_bounds[rank] = v;
    __syncthreads();

    int s = blockIdx.x;
    float b0 = sb[s];
    float b1 = (s < SECT - 1) ? sb[s + 1] : (sb[0] + TWOPI_F);
    float thc = 0.5f * (b0 + b1);
    float c = cosf(thc), sn = sinf(thc);
    if (t < D) {
        float A = pw1[t], B = pw1[D + t];
        bool m = fmaf(A, c, B * sn) > 0.f;
        Am[t] = m ? A : 0.f;
        Bm[t] = m ? B : 0.f;
    }
    __syncthreads();
    int k = t & (D - 1);
    bool dov = t >= D;
    float acc = 0.f;
    #pragma unroll 8
    for (int d = 0; d < D; d++) {
        float w = pw2[d * D + k];
        acc = fmaf(dov ? Bm[d] : Am[d], w, acc);
    }
    if (dov) g_V[s * D + k] = acc;
    else     g_U[s * D + k] = acc;
}

// ---------------- K3: edges — batched metadata + warp-per-edge vector phase -----
__global__ __launch_bounds__(256) void k_edges(const float* __restrict__ x,
                                               const void* __restrict__ ei_raw,
                                               const float* __restrict__ ew, int E) {
    __shared__ float sbound[SECT];
    int t = threadIdx.x;
    sbound[t] = g_bounds[t];
    __syncthreads();
    const long long* ei64 = (const long long*)ei_raw;
    const int*       ei32 = (const int*)ei_raw;
    int is64 = g_ei64;
    int lane = t & 31;
    int wid  = blockIdx.x * 8 + (t >> 5);
    int stride = gridDim.x * 8 * 32;

    for (int e0 = wid * 32; e0 < E; e0 += stride) {
        int e = e0 + lane;
        int src = 0, dst = 0, sct = 0;
        float w0 = 0.f, w1 = 0.f;
        if (e < E) {
            if (is64) { src = (int)ei64[e]; dst = (int)ei64[E + e]; }
            else      { src = ei32[e];      dst = ei32[E + e]; }
            float2 wv = reinterpret_cast<const float2*>(ew)[e];
            w0 = wv.x; w1 = wv.y;
            float th = atan2f(w1, w0);
            int lo = 0, hi = SECT;
            while (lo < hi) {
                int mid = (lo + hi) >> 1;
                if (sbound[mid] <= th) lo = mid + 1; else hi = mid;
            }
            sct = (lo == 0) ? (SECT - 1) : (lo - 1);
            atomicAdd(&g_cnt[dst], 1.f);
        }

        #define EDGE_BODY(i)                                                          \
        {                                                                             \
            int   s_  = __shfl_sync(0xffffffffu, src, (i));                           \
            int   dd_ = __shfl_sync(0xffffffffu, dst, (i));                           \
            int   sc_ = __shfl_sync(0xffffffffu, sct, (i));                           \
            float a0_ = __shfl_sync(0xffffffffu, w0, (i));                            \
            float a1_ = __shfl_sync(0xffffffffu, w1, (i));                            \
            float4 xj = __ldg(reinterpret_cast<const float4*>(x + (size_t)s_ * D) + lane); \
            float4 u4 = __ldg(reinterpret_cast<const float4*>(g_U + sc_ * D) + lane); \
            float4 v4 = __ldg(reinterpret_cast<const float4*>(g_V + sc_ * D) + lane); \
            float4 m;                                                                 \
            m.x = xj.x * fmaf(a0_, u4.x, fmaf(a1_, v4.x, 1.f));                       \
            m.y = xj.y * fmaf(a0_, u4.y, fmaf(a1_, v4.y, 1.f));                       \
            m.z = xj.z * fmaf(a0_, u4.z, fmaf(a1_, v4.z, 1.f));                       \
            m.w = xj.w * fmaf(a0_, u4.w, fmaf(a1_, v4.w, 1.f));                       \
            float* p = g_acc + (size_t)dd_ * D + lane * 4;                            \
            asm volatile("red.global.add.v4.f32 [%0], {%1, %2, %3, %4};"              \
                         :: "l"(p), "f"(m.x), "f"(m.y), "f"(m.z), "f"(m.w) : "memory"); \
        }

        int cnt = E - e0; if (cnt > 32) cnt = 32;
        if (cnt == 32) {
            #pragma unroll 4
            for (int i = 0; i < 32; i++) EDGE_BODY(i)
        } else {
            for (int i = 0; i < cnt; i++) EDGE_BODY(i)
        }
        #undef EDGE_BODY
    }
}

// ---------------- bf16 / mma / ldmatrix helpers ---------------------------------
__device__ __forceinline__ void split_bf16(float a, float& hi, float& lo) {
    hi = __bfloat162float(__float2bfloat16_rn(a));
    lo = a - hi;
}

// bf16x2: .lo = even-k element, .hi = odd-k element
__device__ __forceinline__ unsigned pack_bf16(float even, float odd) {
    unsigned r;
    asm("cvt.rn.bf16x2.f32 %0, %1, %2;" : "=r"(r) : "f"(odd), "f"(even));
    return r;
}

__device__ __forceinline__ void mma_bf16(float* d, unsigned a0, unsigned a1,
                                         unsigned a2, unsigned a3,
                                         unsigned b0, unsigned b1) {
    asm volatile(
        "mma.sync.aligned.m16n8k16.row.col.f32.bf16.bf16.f32 "
        "{%0,%1,%2,%3}, {%4,%5,%6,%7}, {%8,%9}, {%0,%1,%2,%3};\n"
        : "+f"(d[0]), "+f"(d[1]), "+f"(d[2]), "+f"(d[3])
        : "r"(a0), "r"(a1), "r"(a2), "r"(a3), "r"(b0), "r"(b1));
}

__device__ __forceinline__ void ldsm_x4(unsigned& r0, unsigned& r1,
                                        unsigned& r2, unsigned& r3, unsigned addr) {
    asm volatile("ldmatrix.sync.aligned.m8n8.x4.shared.b16 {%0,%1,%2,%3}, [%4];"
                 : "=r"(r0), "=r"(r1), "=r"(r2), "=r"(r3) : "r"(addr));
}

// ---------------- K4: tensor-core GEMM [N,256]@[256,128], 3x bf16-split ---------
// Block 128x128, 8 warps (2M x 4N), warp tile 64x32. Smem holds bf16 H|L packed
// rows (pitch 80 B -> 8 consecutive rows hit 8 distinct 16B bank groups, so
// ldmatrix is conflict-free). Fragments via ldmatrix.x4: 12 LDSM/warp/kt.
#define PITCHW 20   // row pitch in 32-bit words (80 bytes)
__global__ __launch_bounds__(256, 2) void k_gemm(const float* __restrict__ x,
                                                 const float* __restrict__ W,
                                                 const float* __restrict__ bias,
                                                 float* __restrict__ out, int N) {
    __shared__ unsigned sA[128 * PITCHW];   // row m: words 0-7 = H k-pairs, 8-15 = L
    __shared__ unsigned sW[128 * PITCHW];   // row n: words 0-7 = H k-pairs, 8-15 = L
    __shared__ float inv_s[128];
    __shared__ float scol[128], scolq[128];

    int tid = threadIdx.x;
    int row0 = blockIdx.x * 128;
    if (tid < 128) {
        int r = row0 + tid;
        inv_s[tid] = (r < N) ? (1.f / fmaxf(g_cnt[r], 1.f)) : 0.f;
        scol[tid] = 0.f; scolq[tid] = 0.f;
    }

    int lane  = tid & 31;
    int warp  = tid >> 5;
    int warpM = warp >> 2;
    int warpN = warp & 3;
    int grp   = lane >> 2;
    int th4   = lane & 3;

    unsigned sA_base = (unsigned)__cvta_generic_to_shared(sA);
    unsigned sW_base = (unsigned)__cvta_generic_to_shared(sW);

    // ldmatrix source addresses (fixed per thread across kt)
    // A, fragment mi: rows warpM*64+mi*16+(lane&15), k-half byte (lane>>4)*16
    unsigned aAddr = sA_base + (unsigned)((warpM * 64 + (lane & 15)) * 80 + (lane >> 4) * 16);
    // B, pair p (covers ni=2p, 2p+1): quad = lane>>3
    //   n-row = warpN*32 + (p*2 + (quad>>1))*8 + (lane&7); k-half byte (quad&1)*16
    int quad = lane >> 3;
    unsigned bAddr = sW_base + (unsigned)((warpN * 32 + ((quad >> 1) * 8) + (lane & 7)) * 80
                                          + (quad & 1) * 16);

    float c[4][4][4];
    #pragma unroll
    for (int mi = 0; mi < 4; mi++)
        #pragma unroll
        for (int ni = 0; ni < 4; ni++)
            #pragma unroll
            for (int j = 0; j < 4; j++) c[mi][ni][j] = 0.f;

    // A loader: thread handles row m = s>>2, k-chunk ch = s&3 (4 floats = 2 pairs)
    // W loader: thread handles k-row pair kr2=(tid&7)*2, n-chunk n4 = tid>>3
    int a_m0 = tid >> 2, a_ch = tid & 3;
    int w_kr2 = (tid & 7) * 2, w_n4 = tid >> 3;

    __syncthreads();

    for (int kt = 0; kt < 16; kt++) {
        // ---- global loads into registers ----
        float4 av[2];
        #pragma unroll
        for (int u = 0; u < 2; u++) {
            int m = a_m0 + u * 64;
            int r = row0 + m;
            av[u] = make_float4(0.f, 0.f, 0.f, 0.f);
            if (r < N) {
                if (kt < 8) {
                    av[u] = *reinterpret_cast<const float4*>(x + (size_t)r * D + kt * 16 + a_ch * 4);
                } else {
                    float iv = inv_s[m];
                    av[u] = *reinterpret_cast<const float4*>(g_acc + (size_t)r * D + (kt - 8) * 16 + a_ch * 4);
                    av[u].x *= iv; av[u].y *= iv; av[u].z *= iv; av[u].w *= iv;
                }
            }
        }
        float4 w0v = *reinterpret_cast<const float4*>(W + (size_t)(kt * 16 + w_kr2) * D + w_n4 * 4);
        float4 w1v = *reinterpret_cast<const float4*>(W + (size_t)(kt * 16 + w_kr2 + 1) * D + w_n4 * 4);

        __syncthreads();      // previous tile consumed
        // ---- stage A (bf16 H|L packed) ----
        #pragma unroll
        for (int u = 0; u < 2; u++) {
            int m = a_m0 + u * 64;
            float h0, l0, h1, l1, h2, l2, h3, l3;
            split_bf16(av[u].x, h0, l0);
            split_bf16(av[u].y, h1, l1);
            split_bf16(av[u].z, h2, l2);
            split_bf16(av[u].w, h3, l3);
            int base = m * PITCHW + a_ch * 2;
            *reinterpret_cast<uint2*>(&sA[base])     = make_uint2(pack_bf16(h0, h1), pack_bf16(h2, h3));
            *reinterpret_cast<uint2*>(&sA[base + 8]) = make_uint2(pack_bf16(l0, l1), pack_bf16(l2, l3));
        }
        // ---- stage W transposed (n-row major, k-pairs packed) ----
        {
            float wh0, wl0, wh1, wl1;
            int kp = w_kr2 >> 1;
            #pragma unroll
            for (int j = 0; j < 4; j++) {
                float e = (j == 0) ? w0v.x : (j == 1) ? w0v.y : (j == 2) ? w0v.z : w0v.w;
                float o = (j == 0) ? w1v.x : (j == 1) ? w1v.y : (j == 2) ? w1v.z : w1v.w;
                split_bf16(e, wh0, wl0);
                split_bf16(o, wh1, wl1);
                int nr = w_n4 * 4 + j;
                sW[nr * PITCHW + kp]     = pack_bf16(wh0, wh1);
                sW[nr * PITCHW + 8 + kp] = pack_bf16(wl0, wl1);
            }
        }
        __syncthreads();

        // ---- fragments via ldmatrix + mma ----
        unsigned bH[4][2], bL[4][2];
        #pragma unroll
        for (int p = 0; p < 2; p++) {
            unsigned off = (unsigned)(p * 16 * 80);
            ldsm_x4(bH[2*p][0], bH[2*p][1], bH[2*p+1][0], bH[2*p+1][1], bAddr + off);
            ldsm_x4(bL[2*p][0], bL[2*p][1], bL[2*p+1][0], bL[2*p+1][1], bAddr + off + 32);
        }
        #pragma unroll
        for (int mi = 0; mi < 4; mi++) {
            unsigned off = (unsigned)(mi * 16 * 80);
            unsigned aH0, aH1, aH2, aH3, aL0, aL1, aL2, aL3;
            ldsm_x4(aH0, aH1, aH2, aH3, aAddr + off);
            ldsm_x4(aL0, aL1, aL2, aL3, aAddr + off + 32);
            #pragma unroll
            for (int ni = 0; ni < 4; ni++) {
                mma_bf16(c[mi][ni], aH0, aH1, aH2, aH3, bH[ni][0], bH[ni][1]);
                mma_bf16(c[mi][ni], aH0, aH1, aH2, aH3, bL[ni][0], bL[ni][1]);
                mma_bf16(c[mi][ni], aL0, aL1, aL2, aL3, bH[ni][0], bH[ni][1]);
            }
        }
    }

    // ---- epilogue: bias + store + BN stats ----
    float ss[4][2], qq[4][2];
    #pragma unroll
    for (int ni = 0; ni < 4; ni++) { ss[ni][0]=ss[ni][1]=qq[ni][0]=qq[ni][1]=0.f; }

    #pragma unroll
    for (int ni = 0; ni < 4; ni++) {
        int col = warpN * 32 + ni * 8 + 2 * th4;
        float b0 = __ldg(bias + col), b1 = __ldg(bias + col + 1);
        #pragma unroll
        for (int mi = 0; mi < 4; mi++) {
            int rlo = row0 + warpM * 64 + mi * 16 + grp;
            if (rlo < N) {
                float v0 = c[mi][ni][0] + b0;
                float v1 = c[mi][ni][1] + b1;
                *reinterpret_cast<float2*>(out + (size_t)rlo * D + col) = make_float2(v0, v1);
                ss[ni][0] += v0; qq[ni][0] += v0 * v0;
                ss[ni][1] += v1; qq[ni][1] += v1 * v1;
            }
            int rhi = rlo + 8;
            if (rhi < N) {
                float v2 = c[mi][ni][2] + b0;
                float v3 = c[mi][ni][3] + b1;
                *reinterpret_cast<float2*>(out + (size_t)rhi * D + col) = make_float2(v2, v3);
                ss[ni][0] += v2; qq[ni][0] += v2 * v2;
                ss[ni][1] += v3; qq[ni][1] += v3 * v3;
            }
        }
    }
    #pragma unroll
    for (int ni = 0; ni < 4; ni++)
        #pragma unroll
        for (int j = 0; j < 2; j++) {
            float s = ss[ni][j], q = qq[ni][j];
            #pragma unroll
            for (int off = 4; off < 32; off <<= 1) {
                s += __shfl_xor_sync(0xffffffffu, s, off);
                q += __shfl_xor_sync(0xffffffffu, q, off);
            }
            if (lane < 4) {
                int col = warpN * 32 + ni * 8 + 2 * lane + j;
                atomicAdd(&scol[col],  s);
                atomicAdd(&scolq[col], q);
            }
        }
    __syncthreads();
    if (tid < D) {
        atomicAdd(&g_colsum[tid], scol[tid]);
        atomicAdd(&g_colsq[tid],  scolq[tid]);
    }
}

// ---------------- K5: BN finalize + relu + residual -----------------------------
__global__ void k_bn(const float* __restrict__ x, const float* __restrict__ gamma,
                     const float* __restrict__ beta, float* __restrict__ out, int N) {
    __shared__ float ssc[D], ssh[D];
    int t = threadIdx.x;
    if (t < D) {
        float invN = 1.f / (float)N;
        float mean = g_colsum[t] * invN;
        float var  = g_colsq[t] * invN - mean * mean;
        float sc = gamma[t] * rsqrtf(var + 1e-5f);
        ssc[t] = sc;
        ssh[t] = beta[t] - mean * sc;
    }
    __syncthreads();
    int i = blockIdx.x * blockDim.x + t;
    int tot = N * (D / 4);
    if (i < tot) {
        int c = (i & 31) * 4;
        float4 o  = reinterpret_cast<float4*>(out)[i];
        float4 xr = reinterpret_cast<const float4*>(x)[i];
        o.x = fmaxf(fmaf(o.x, ssc[c + 0], ssh[c + 0]), 0.f) + xr.x;
        o.y = fmaxf(fmaf(o.y, ssc[c + 1], ssh[c + 1]), 0.f) + xr.y;
        o.z = fmaxf(fmaf(o.z, ssc[c + 2], ssh[c + 2]), 0.f) + xr.z;
        o.w = fmaxf(fmaf(o.w, ssc[c + 3], ssh[c + 3]), 0.f) + xr.w;
        reinterpret_cast<float4*>(out)[i] = o;
    }
}

// ---------------- launch --------------------------------------------------------
extern "C" void kernel_launch(void* const* d_in, const int* in_sizes, int n_in,
                              void* d_out, int out_size) {
    const float* x     = (const float*)d_in[0];
    const void*  ei    = d_in[1];
    const float* ew    = (const float*)d_in[2];
    const float* pw1   = (const float*)d_in[3];
    const float* pw2   = (const float*)d_in[4];
    const float* sw    = (const float*)d_in[5];
    const float* sb    = (const float*)d_in[6];
    const float* gamma = (const float*)d_in[7];
    const float* beta  = (const float*)d_in[8];
    float* out = (float*)d_out;

    int N = in_sizes[0] / D;
    int E = in_sizes[1] / 2;

    k_zero<<<4096, 256>>>((const int*)ei, N);
    k_sectors<<<SECT, 256>>>(pw1, pw2);
    k_edges<<<4096, 256>>>(x, ei, ew, E);
    k_gemm<<<(N + 127) / 128, 256>>>(x, sw, sb, out, N);
    k_bn<<<(N * (D / 4) + 255) / 256, 256>>>(x, gamma, beta, out, N);
}

// round 12
// speedup vs baseline: 1.4020x; 1.0143x over previous
#include <cuda_runtime.h>
#include <cuda_bf16.h>
#include <math.h>
#include <stdint.h>

#define D 128
#define NMAX 100000
#define SECT 256

#define PI_F      3.14159265358979f
#define HALFPI_F  1.57079632679490f
#define TWOPI_F   6.28318530717959f

// ---------------- scratch (static device globals; no runtime alloc) ------------
__device__ float g_acc[(size_t)NMAX * D];   // 51.2 MB scatter accumulator
__device__ float g_cnt[NMAX];               // per-dst edge counts
__device__ float g_bounds[SECT];            // sorted sector boundary angles
__device__ float g_U[SECT * D];             // sector tables: pe = w0*U[s] + w1*V[s]
__device__ float g_V[SECT * D];
__device__ float g_colsum[D];               // BN stats
__device__ float g_colsq[D];
__device__ int   g_ei64;                    // 1 if edge_index is int64

// ---------------- K0: zero scratch + edge-index dtype detect --------------------
__global__ void k_zero(const int* __restrict__ w, int n) {
    if (blockIdx.x == 0 && threadIdx.x == 0) {
        int all0 = 1;
        #pragma unroll
        for (int j = 1; j < 64; j += 2) all0 &= (w[j] == 0);
        g_ei64 = all0;
    }
    int nd4 = n * (D / 4);
    float4 z = make_float4(0.f, 0.f, 0.f, 0.f);
    int stride = gridDim.x * blockDim.x;
    for (int i = blockIdx.x * blockDim.x + threadIdx.x; i < nd4; i += stride)
        reinterpret_cast<float4*>(g_acc)[i] = z;
    for (int i = blockIdx.x * blockDim.x + threadIdx.x; i < n; i += stride)
        g_cnt[i] = 0.f;
    if (blockIdx.x == 0 && threadIdx.x < D) {
        g_colsum[threadIdx.x] = 0.f;
        g_colsq[threadIdx.x]  = 0.f;
    }
}

// ---------------- K1: bounds + sector tables (merged; 256 blocks x 256 thr) -----
__global__ __launch_bounds__(256) void k_sectors(const float* __restrict__ pw1,
                                                 const float* __restrict__ pw2) {
    __shared__ float raw[SECT];
    __shared__ float sb[SECT];
    __shared__ float Am[D], Bm[D];
    int t = threadIdx.x;
    if (t < D) {
        float A = pw1[t];
        float B = pw1[D + t];
        float phi = atan2f(B, A);
        float c0 = phi + HALFPI_F; if (c0 >  PI_F) c0 -= TWOPI_F;
        float c1 = phi - HALFPI_F; if (c1 < -PI_F) c1 += TWOPI_F;
        raw[2 * t]     = c0;
        raw[2 * t + 1] = c1;
    }
    __syncthreads();
    float v = raw[t];
    int rank = 0;
    #pragma unroll 8
    for (int j = 0; j < SECT; j++) {
        float u = raw[j];
        rank += (u < v) || (u == v && j < t);
    }
    sb[rank] = v;
    if (blockIdx.x == 0) g_bounds[rank] = v;
    __syncthreads();

    int s = blockIdx.x;
    float b0 = sb[s];
    float b1 = (s < SECT - 1) ? sb[s + 1] : (sb[0] + TWOPI_F);
    float thc = 0.5f * (b0 + b1);
    float c = cosf(thc), sn = sinf(thc);
    if (t < D) {
        float A = pw1[t], B = pw1[D + t];
        bool m = fmaf(A, c, B * sn) > 0.f;
        Am[t] = m ? A : 0.f;
        Bm[t] = m ? B : 0.f;
    }
    __syncthreads();
    int k = t & (D - 1);
    bool dov = t >= D;
    float acc = 0.f;
    #pragma unroll 8
    for (int d = 0; d < D; d++) {
        float w = pw2[d * D + k];
        acc = fmaf(dov ? Bm[d] : Am[d], w, acc);
    }
    if (dov) g_V[s * D + k] = acc;
    else     g_U[s * D + k] = acc;
}

// ---------------- K3: edges — batched metadata + warp-per-edge vector phase -----
__global__ __launch_bounds__(256) void k_edges(const float* __restrict__ x,
                                               const void* __restrict__ ei_raw,
                                               const float* __restrict__ ew, int E) {
    __shared__ float sbound[SECT];
    int t = threadIdx.x;
    sbound[t] = g_bounds[t];
    __syncthreads();
    const long long* ei64 = (const long long*)ei_raw;
    const int*       ei32 = (const int*)ei_raw;
    int is64 = g_ei64;
    int lane = t & 31;
    int wid  = blockIdx.x * 8 + (t >> 5);
    int stride = gridDim.x * 8 * 32;

    for (int e0 = wid * 32; e0 < E; e0 += stride) {
        int e = e0 + lane;
        int src = 0, dst = 0, sct = 0;
        float w0 = 0.f, w1 = 0.f;
        if (e < E) {
            if (is64) { src = (int)ei64[e]; dst = (int)ei64[E + e]; }
            else      { src = ei32[e];      dst = ei32[E + e]; }
            float2 wv = reinterpret_cast<const float2*>(ew)[e];
            w0 = wv.x; w1 = wv.y;
            float th = atan2f(w1, w0);
            int lo = 0, hi = SECT;
            while (lo < hi) {
                int mid = (lo + hi) >> 1;
                if (sbound[mid] <= th) lo = mid + 1; else hi = mid;
            }
            sct = (lo == 0) ? (SECT - 1) : (lo - 1);
            atomicAdd(&g_cnt[dst], 1.f);
        }

        #define EDGE_BODY(i)                                                          \
        {                                                                             \
            int   s_  = __shfl_sync(0xffffffffu, src, (i));                           \
            int   dd_ = __shfl_sync(0xffffffffu, dst, (i));                           \
            int   sc_ = __shfl_sync(0xffffffffu, sct, (i));                           \
            float a0_ = __shfl_sync(0xffffffffu, w0, (i));                            \
            float a1_ = __shfl_sync(0xffffffffu, w1, (i));                            \
            float4 xj = __ldg(reinterpret_cast<const float4*>(x + (size_t)s_ * D) + lane); \
            float4 u4 = __ldg(reinterpret_cast<const float4*>(g_U + sc_ * D) + lane); \
            float4 v4 = __ldg(reinterpret_cast<const float4*>(g_V + sc_ * D) + lane); \
            float4 m;                                                                 \
            m.x = xj.x * fmaf(a0_, u4.x, fmaf(a1_, v4.x, 1.f));                       \
            m.y = xj.y * fmaf(a0_, u4.y, fmaf(a1_, v4.y, 1.f));                       \
            m.z = xj.z * fmaf(a0_, u4.z, fmaf(a1_, v4.z, 1.f));                       \
            m.w = xj.w * fmaf(a0_, u4.w, fmaf(a1_, v4.w, 1.f));                       \
            float* p = g_acc + (size_t)dd_ * D + lane * 4;                            \
            asm volatile("red.global.add.v4.f32 [%0], {%1, %2, %3, %4};"              \
                         :: "l"(p), "f"(m.x), "f"(m.y), "f"(m.z), "f"(m.w) : "memory"); \
        }

        int cnt = E - e0; if (cnt > 32) cnt = 32;
        if (cnt == 32) {
            #pragma unroll 4
            for (int i = 0; i < 32; i++) EDGE_BODY(i)
        } else {
            for (int i = 0; i < cnt; i++) EDGE_BODY(i)
        }
        #undef EDGE_BODY
    }
}

// ---------------- bf16 / mma / ldmatrix helpers ---------------------------------
__device__ __forceinline__ void split_bf16(float a, float& hi, float& lo) {
    hi = __bfloat162float(__float2bfloat16_rn(a));
    lo = a - hi;
}

__device__ __forceinline__ unsigned pack_bf16(float even, float odd) {
    unsigned r;
    asm("cvt.rn.bf16x2.f32 %0, %1, %2;" : "=r"(r) : "f"(odd), "f"(even));
    return r;
}

__device__ __forceinline__ void mma_bf16(float* d, unsigned a0, unsigned a1,
                                         unsigned a2, unsigned a3,
                                         unsigned b0, unsigned b1) {
    asm volatile(
        "mma.sync.aligned.m16n8k16.row.col.f32.bf16.bf16.f32 "
        "{%0,%1,%2,%3}, {%4,%5,%6,%7}, {%8,%9}, {%0,%1,%2,%3};\n"
        : "+f"(d[0]), "+f"(d[1]), "+f"(d[2]), "+f"(d[3])
        : "r"(a0), "r"(a1), "r"(a2), "r"(a3), "r"(b0), "r"(b1));
}

__device__ __forceinline__ void ldsm_x4(unsigned& r0, unsigned& r1,
                                        unsigned& r2, unsigned& r3, unsigned addr) {
    asm volatile("ldmatrix.sync.aligned.m8n8.x4.shared.b16 {%0,%1,%2,%3}, [%4];"
                 : "=r"(r0), "=r"(r1), "=r"(r2), "=r"(r3) : "r"(addr));
}

// ---------------- K4: tensor-core GEMM, bf16 3-pass, double-buffered ------------
// Block 128x128, 8 warps (2M x 4N). Two smem stages; ONE barrier per k-tile:
//   LDG(kt+1) -> LDSM+MMA(kt) from buf[kt&1] -> STS(kt+1) to buf[1-kt&1] -> bar.
#define PITCHW 20                    // row pitch in words (80 B)
#define BUFW   (128 * PITCHW)        // words per buffer (10240 = 40 KB x2 arrays)
__global__ __launch_bounds__(256, 2) void k_gemm(const float* __restrict__ x,
                                                 const float* __restrict__ W,
                                                 const float* __restrict__ bias,
                                                 float* __restrict__ out, int N) {
    __shared__ unsigned sA[2 * BUFW];
    __shared__ unsigned sW[2 * BUFW];
    __shared__ float inv_s[128];
    __shared__ float scol[128], scolq[128];

    int tid = threadIdx.x;
    int row0 = blockIdx.x * 128;
    if (tid < 128) {
        int r = row0 + tid;
        inv_s[tid] = (r < N) ? (1.f / fmaxf(g_cnt[r], 1.f)) : 0.f;
        scol[tid] = 0.f; scolq[tid] = 0.f;
    }

    int lane  = tid & 31;
    int warp  = tid >> 5;
    int warpM = warp >> 2;
    int warpN = warp & 3;
    int grp   = lane >> 2;
    int th4   = lane & 3;

    unsigned sA_base = (unsigned)__cvta_generic_to_shared(sA);
    unsigned sW_base = (unsigned)__cvta_generic_to_shared(sW);
    unsigned aAddr = sA_base + (unsigned)((warpM * 64 + (lane & 15)) * 80 + (lane >> 4) * 16);
    int quad = lane >> 3;
    unsigned bAddr = sW_base + (unsigned)((warpN * 32 + ((quad >> 1) * 8) + (lane & 7)) * 80
                                          + (quad & 1) * 16);

    float c[4][4][4];
    #pragma unroll
    for (int mi = 0; mi < 4; mi++)
        #pragma unroll
        for (int ni = 0; ni < 4; ni++)
            #pragma unroll
            for (int j = 0; j < 4; j++) c[mi][ni][j] = 0.f;

    int a_m0 = tid >> 2, a_ch = tid & 3;
    int w_kr2 = (tid & 7) * 2, w_n4 = tid >> 3;

    __syncthreads();   // inv_s ready

    float4 av[2]; float4 w0v, w1v;

    // ---- load helpers (macros keep register staging identical each use) ----
    #define LOAD_TILE(kt)                                                             \
    {                                                                                 \
        _Pragma("unroll")                                                             \
        for (int u = 0; u < 2; u++) {                                                 \
            int m = a_m0 + u * 64;                                                    \
            int r = row0 + m;                                                         \
            av[u] = make_float4(0.f, 0.f, 0.f, 0.f);                                  \
            if (r < N) {                                                              \
                if ((kt) < 8) {                                                       \
                    av[u] = *reinterpret_cast<const float4*>(x + (size_t)r * D + (kt) * 16 + a_ch * 4); \
                } else {                                                              \
                    float iv = inv_s[m];                                              \
                    av[u] = *reinterpret_cast<const float4*>(g_acc + (size_t)r * D + ((kt) - 8) * 16 + a_ch * 4); \
                    av[u].x *= iv; av[u].y *= iv; av[u].z *= iv; av[u].w *= iv;       \
                }                                                                     \
            }                                                                         \
        }                                                                             \
        w0v = *reinterpret_cast<const float4*>(W + (size_t)((kt) * 16 + w_kr2) * D + w_n4 * 4); \
        w1v = *reinterpret_cast<const float4*>(W + (size_t)((kt) * 16 + w_kr2 + 1) * D + w_n4 * 4); \
    }

    #define STAGE_TILE(buf)                                                           \
    {                                                                                 \
        unsigned* dA = sA + (buf) * BUFW;                                             \
        unsigned* dW = sW + (buf) * BUFW;                                             \
        _Pragma("unroll")                                                             \
        for (int u = 0; u < 2; u++) {                                                 \
            int m = a_m0 + u * 64;                                                    \
            float h0, l0, h1, l1, h2, l2, h3, l3;                                     \
            split_bf16(av[u].x, h0, l0);                                              \
            split_bf16(av[u].y, h1, l1);                                              \
            split_bf16(av[u].z, h2, l2);                                              \
            split_bf16(av[u].w, h3, l3);                                              \
            int base = m * PITCHW + a_ch * 2;                                         \
            *reinterpret_cast<uint2*>(&dA[base])     = make_uint2(pack_bf16(h0, h1), pack_bf16(h2, h3)); \
            *reinterpret_cast<uint2*>(&dA[base + 8]) = make_uint2(pack_bf16(l0, l1), pack_bf16(l2, l3)); \
        }                                                                             \
        {                                                                             \
            float wh0, wl0, wh1, wl1;                                                 \
            int kp = w_kr2 >> 1;                                                      \
            _Pragma("unroll")                                                         \
            for (int j = 0; j < 4; j++) {                                             \
                float e = (j == 0) ? w0v.x : (j == 1) ? w0v.y : (j == 2) ? w0v.z : w0v.w; \
                float o = (j == 0) ? w1v.x : (j == 1) ? w1v.y : (j == 2) ? w1v.z : w1v.w; \
                split_bf16(e, wh0, wl0);                                              \
                split_bf16(o, wh1, wl1);                                              \
                int nr = w_n4 * 4 + j;                                                \
                dW[nr * PITCHW + kp]     = pack_bf16(wh0, wh1);                       \
                dW[nr * PITCHW + 8 + kp] = pack_bf16(wl0, wl1);                       \
            }                                                                         \
        }                                                                             \
    }

    // prologue: tile 0
    LOAD_TILE(0)
    STAGE_TILE(0)
    __syncthreads();

    for (int kt = 0; kt < 16; kt++) {
        if (kt < 15) LOAD_TILE(kt + 1)          // in flight during MMA below

        unsigned bufOff = (unsigned)((kt & 1) * BUFW * 4);
        unsigned bH[4][2], bL[4][2];
        #pragma unroll
        for (int p = 0; p < 2; p++) {
            unsigned off = bufOff + (unsigned)(p * 16 * 80);
            ldsm_x4(bH[2*p][0], bH[2*p][1], bH[2*p+1][0], bH[2*p+1][1], bAddr + off);
            ldsm_x4(bL[2*p][0], bL[2*p][1], bL[2*p+1][0], bL[2*p+1][1], bAddr + off + 32);
        }
        #pragma unroll
        for (int mi = 0; mi < 4; mi++) {
            unsigned off = bufOff + (unsigned)(mi * 16 * 80);
            unsigned aH0, aH1, aH2, aH3, aL0, aL1, aL2, aL3;
            ldsm_x4(aH0, aH1, aH2, aH3, aAddr + off);
            ldsm_x4(aL0, aL1, aL2, aL3, aAddr + off + 32);
            #pragma unroll
            for (int ni = 0; ni < 4; ni++) {
                mma_bf16(c[mi][ni], aH0, aH1, aH2, aH3, bH[ni][0], bH[ni][1]);
                mma_bf16(c[mi][ni], aH0, aH1, aH2, aH3, bL[ni][0], bL[ni][1]);
                mma_bf16(c[mi][ni], aL0, aL1, aL2, aL3, bH[ni][0], bH[ni][1]);
            }
        }

        if (kt < 15) STAGE_TILE((kt + 1) & 1)
        __syncthreads();
    }
    #undef LOAD_TILE
    #undef STAGE_TILE

    // ---- epilogue: bias + store + BN stats ----
    float ss[4][2], qq[4][2];
    #pragma unroll
    for (int ni = 0; ni < 4; ni++) { ss[ni][0]=ss[ni][1]=qq[ni][0]=qq[ni][1]=0.f; }

    #pragma unroll
    for (int ni = 0; ni < 4; ni++) {
        int col = warpN * 32 + ni * 8 + 2 * th4;
        float b0 = __ldg(bias + col), b1 = __ldg(bias + col + 1);
        #pragma unroll
        for (int mi = 0; mi < 4; mi++) {
            int rlo = row0 + warpM * 64 + mi * 16 + grp;
            if (rlo < N) {
                float v0 = c[mi][ni][0] + b0;
                float v1 = c[mi][ni][1] + b1;
                *reinterpret_cast<float2*>(out + (size_t)rlo * D + col) = make_float2(v0, v1);
                ss[ni][0] += v0; qq[ni][0] += v0 * v0;
                ss[ni][1] += v1; qq[ni][1] += v1 * v1;
            }
            int rhi = rlo + 8;
            if (rhi < N) {
                float v2 = c[mi][ni][2] + b0;
                float v3 = c[mi][ni][3] + b1;
                *reinterpret_cast<float2*>(out + (size_t)rhi * D + col) = make_float2(v2, v3);
                ss[ni][0] += v2; qq[ni][0] += v2 * v2;
                ss[ni][1] += v3; qq[ni][1] += v3 * v3;
            }
        }
    }
    #pragma unroll
    for (int ni = 0; ni < 4; ni++)
        #pragma unroll
        for (int j = 0; j < 2; j++) {
            float s = ss[ni][j], q = qq[ni][j];
            #pragma unroll
            for (int off = 4; off < 32; off <<= 1) {
                s += __shfl_xor_sync(0xffffffffu, s, off);
                q += __shfl_xor_sync(0xffffffffu, q, off);
            }
            if (lane < 4) {
                int col = warpN * 32 + ni * 8 + 2 * lane + j;
                atomicAdd(&scol[col],  s);
                atomicAdd(&scolq[col], q);
            }
        }
    __syncthreads();
    if (tid < D) {
        atomicAdd(&g_colsum[tid], scol[tid]);
        atomicAdd(&g_colsq[tid],  scolq[tid]);
    }
}

// ---------------- K5: BN finalize + relu + residual -----------------------------
__global__ void k_bn(const float* __restrict__ x, const float* __restrict__ gamma,
                     const float* __restrict__ beta, float* __restrict__ out, int N) {
    __shared__ float ssc[D], ssh[D];
    int t = threadIdx.x;
    if (t < D) {
        float invN = 1.f / (float)N;
        float mean = g_colsum[t] * invN;
        float var  = g_colsq[t] * invN - mean * mean;
        float sc = gamma[t] * rsqrtf(var + 1e-5f);
        ssc[t] = sc;
        ssh[t] = beta[t] - mean * sc;
    }
    __syncthreads();
    int i = blockIdx.x * blockDim.x + t;
    int tot = N * (D / 4);
    if (i < tot) {
        int c = (i & 31) * 4;
        float4 o  = reinterpret_cast<float4*>(out)[i];
        float4 xr = reinterpret_cast<const float4*>(x)[i];
        o.x = fmaxf(fmaf(o.x, ssc[c + 0], ssh[c + 0]), 0.f) + xr.x;
        o.y = fmaxf(fmaf(o.y, ssc[c + 1], ssh[c + 1]), 0.f) + xr.y;
        o.z = fmaxf(fmaf(o.z, ssc[c + 2], ssh[c + 2]), 0.f) + xr.z;
        o.w = fmaxf(fmaf(o.w, ssc[c + 3], ssh[c + 3]), 0.f) + xr.w;
        reinterpret_cast<float4*>(out)[i] = o;
    }
}

// ---------------- launch --------------------------------------------------------
extern "C" void kernel_launch(void* const* d_in, const int* in_sizes, int n_in,
                              void* d_out, int out_size) {
    const float* x     = (const float*)d_in[0];
    const void*  ei    = d_in[1];
    const float* ew    = (const float*)d_in[2];
    const float* pw1   = (const float*)d_in[3];
    const float* pw2   = (const float*)d_in[4];
    const float* sw    = (const float*)d_in[5];
    const float* sb    = (const float*)d_in[6];
    const float* gamma = (const float*)d_in[7];
    const float* beta  = (const float*)d_in[8];
    float* out = (float*)d_out;

    int N = in_sizes[0] / D;
    int E = in_sizes[1] / 2;

    k_zero<<<4096, 256>>>((const int*)ei, N);
    k_sectors<<<SECT, 256>>>(pw1, pw2);
    k_edges<<<4096, 256>>>(x, ei, ew, E);
    k_gemm<<<(N + 127) / 128, 256>>>(x, sw, sb, out, N);
    k_bn<<<(N * (D / 4) + 255) / 256, 256>>>(x, gamma, beta, out, N);
}

// round 14
// speedup vs baseline: 1.5429x; 1.1005x over previous
#include <cuda_runtime.h>
#include <cuda_bf16.h>
#include <cuda_fp16.h>
#include <math.h>
#include <stdint.h>

#define D 128
#define NMAX 100000
#define SECT 256

#define PI_F      3.14159265358979f
#define HALFPI_F  1.57079632679490f
#define TWOPI_F   6.28318530717959f

// ---------------- scratch (static device globals; no runtime alloc) ------------
__device__ float g_acc[(size_t)NMAX * D];   // 51.2 MB scatter accumulator
__device__ float g_cnt[NMAX];               // per-dst edge counts
__device__ float g_bounds[SECT];            // sorted sector boundary angles
__device__ __half2 g_UVh[SECT * D];         // sector tables, fp16 (U,V) pairs
__device__ float g_colsum[D];               // BN stats
__device__ float g_colsq[D];
__device__ int   g_ei64;                    // 1 if edge_index is int64
__device__ unsigned g_Wpk[16 * 2048];       // W pre-split bf16 H|L pairs per k-tile

// ---------------- K0: zero scratch + edge-index dtype detect --------------------
__global__ void k_zero(const int* __restrict__ w, int n) {
    if (blockIdx.x == 0 && threadIdx.x == 0) {
        int all0 = 1;
        #pragma unroll
        for (int j = 1; j < 64; j += 2) all0 &= (w[j] == 0);
        g_ei64 = all0;
    }
    int nd4 = n * (D / 4);
    float4 z = make_float4(0.f, 0.f, 0.f, 0.f);
    int stride = gridDim.x * blockDim.x;
    for (int i = blockIdx.x * blockDim.x + threadIdx.x; i < nd4; i += stride)
        reinterpret_cast<float4*>(g_acc)[i] = z;
    for (int i = blockIdx.x * blockDim.x + threadIdx.x; i < n; i += stride)
        g_cnt[i] = 0.f;
    if (blockIdx.x == 0 && threadIdx.x < D) {
        g_colsum[threadIdx.x] = 0.f;
        g_colsq[threadIdx.x]  = 0.f;
    }
}

// ---------------- bf16 helpers --------------------------------------------------
__device__ __forceinline__ void split_bf16(float a, float& hi, float& lo) {
    hi = __bfloat162float(__float2bfloat16_rn(a));
    lo = a - hi;
}
__device__ __forceinline__ unsigned pack_bf16(float even, float odd) {
    unsigned r;
    asm("cvt.rn.bf16x2.f32 %0, %1, %2;" : "=r"(r) : "f"(odd), "f"(even));
    return r;
}

// ---------------- K1: bounds + sector tables (merged; 256 blocks x 256 thr) -----
__global__ __launch_bounds__(256) void k_sectors(const float* __restrict__ pw1,
                                                 const float* __restrict__ pw2) {
    __shared__ float raw[SECT];
    __shared__ float sb[SECT];
    __shared__ float Am[D], Bm[D];
    __shared__ float su[D], sv[D];
    int t = threadIdx.x;
    if (t < D) {
        float A = pw1[t];
        float B = pw1[D + t];
        float phi = atan2f(B, A);
        float c0 = phi + HALFPI_F; if (c0 >  PI_F) c0 -= TWOPI_F;
        float c1 = phi - HALFPI_F; if (c1 < -PI_F) c1 += TWOPI_F;
        raw[2 * t]     = c0;
        raw[2 * t + 1] = c1;
    }
    __syncthreads();
    float v = raw[t];
    int rank = 0;
    #pragma unroll 8
    for (int j = 0; j < SECT; j++) {
        float u = raw[j];
        rank += (u < v) || (u == v && j < t);
    }
    sb[rank] = v;
    if (blockIdx.x == 0) g_bounds[rank] = v;
    __syncthreads();

    int s = blockIdx.x;
    float b0 = sb[s];
    float b1 = (s < SECT - 1) ? sb[s + 1] : (sb[0] + TWOPI_F);
    float thc = 0.5f * (b0 + b1);
    float c = cosf(thc), sn = sinf(thc);
    if (t < D) {
        float A = pw1[t], B = pw1[D + t];
        bool m = fmaf(A, c, B * sn) > 0.f;
        Am[t] = m ? A : 0.f;
        Bm[t] = m ? B : 0.f;
    }
    __syncthreads();
    int k = t & (D - 1);
    bool dov = t >= D;
    float acc = 0.f;
    #pragma unroll 8
    for (int d = 0; d < D; d++) {
        float w = pw2[d * D + k];
        acc = fmaf(dov ? Bm[d] : Am[d], w, acc);
    }
    if (dov) sv[k] = acc;
    else     su[k] = acc;
    __syncthreads();
    if (t < D) g_UVh[s * D + t] = __floats2half2_rn(su[t], sv[t]);
}

// ---------------- K2b: W pre-split into packed bf16 H|L pair tiles --------------
// g_Wpk[kt][n][kp]   = bf16x2(H(W[kt*16+2kp][n]), H(W[kt*16+2kp+1][n]))
// g_Wpk[kt][n][8+kp] = same with L parts. Row n = 16 words.
__global__ void k_wprep(const float* __restrict__ W) {
    int idx = blockIdx.x * blockDim.x + threadIdx.x;   // 16*128*8
    if (idx < 16 * 128 * 8) {
        int kt = idx >> 10;
        int n  = (idx >> 3) & 127;
        int kp = idx & 7;
        float e = W[(size_t)(kt * 16 + 2 * kp) * D + n];
        float o = W[(size_t)(kt * 16 + 2 * kp + 1) * D + n];
        float eh, el, oh, ol;
        split_bf16(e, eh, el);
        split_bf16(o, oh, ol);
        g_Wpk[kt * 2048 + n * 16 + kp]     = pack_bf16(eh, oh);
        g_Wpk[kt * 2048 + n * 16 + 8 + kp] = pack_bf16(el, ol);
    }
}

// ---------------- K3: edges — fp16 UV table, batched metadata -------------------
__global__ __launch_bounds__(256) void k_edges(const float* __restrict__ x,
                                               const void* __restrict__ ei_raw,
                                               const float* __restrict__ ew, int E) {
    __shared__ float sbound[SECT];
    int t = threadIdx.x;
    sbound[t] = g_bounds[t];
    __syncthreads();
    const long long* ei64 = (const long long*)ei_raw;
    const int*       ei32 = (const int*)ei_raw;
    int is64 = g_ei64;
    int lane = t & 31;
    int wid  = blockIdx.x * 8 + (t >> 5);
    int stride = gridDim.x * 8 * 32;

    for (int e0 = wid * 32; e0 < E; e0 += stride) {
        int e = e0 + lane;
        int src = 0, dst = 0, sct = 0;
        float w0 = 0.f, w1 = 0.f;
        if (e < E) {
            if (is64) { src = (int)ei64[e]; dst = (int)ei64[E + e]; }
            else      { src = ei32[e];      dst = ei32[E + e]; }
            float2 wv = reinterpret_cast<const float2*>(ew)[e];
            w0 = wv.x; w1 = wv.y;
            float th = atan2f(w1, w0);
            int lo = 0, hi = SECT;
            while (lo < hi) {
                int mid = (lo + hi) >> 1;
                if (sbound[mid] <= th) lo = mid + 1; else hi = mid;
            }
            sct = (lo == 0) ? (SECT - 1) : (lo - 1);
            atomicAdd(&g_cnt[dst], 1.f);
        }

        #define EDGE_BODY(i)                                                          \
        {                                                                             \
            int   s_  = __shfl_sync(0xffffffffu, src, (i));                           \
            int   dd_ = __shfl_sync(0xffffffffu, dst, (i));                           \
            int   sc_ = __shfl_sync(0xffffffffu, sct, (i));                           \
            float a0_ = __shfl_sync(0xffffffffu, w0, (i));                            \
            float a1_ = __shfl_sync(0xffffffffu, w1, (i));                            \
            float4 xj = __ldg(reinterpret_cast<const float4*>(x + (size_t)s_ * D) + lane); \
            uint4 uvr = __ldg(reinterpret_cast<const uint4*>(g_UVh + (size_t)sc_ * D) + lane); \
            float2 p0 = __half22float2(*reinterpret_cast<__half2*>(&uvr.x));          \
            float2 p1 = __half22float2(*reinterpret_cast<__half2*>(&uvr.y));          \
            float2 p2 = __half22float2(*reinterpret_cast<__half2*>(&uvr.z));          \
            float2 p3 = __half22float2(*reinterpret_cast<__half2*>(&uvr.w));          \
            float4 m;                                                                 \
            m.x = xj.x * fmaf(a0_, p0.x, fmaf(a1_, p0.y, 1.f));                       \
            m.y = xj.y * fmaf(a0_, p1.x, fmaf(a1_, p1.y, 1.f));                       \
            m.z = xj.z * fmaf(a0_, p2.x, fmaf(a1_, p2.y, 1.f));                       \
            m.w = xj.w * fmaf(a0_, p3.x, fmaf(a1_, p3.y, 1.f));                       \
            float* p = g_acc + (size_t)dd_ * D + lane * 4;                            \
            asm volatile("red.global.add.v4.f32 [%0], {%1, %2, %3, %4};"              \
                         :: "l"(p), "f"(m.x), "f"(m.y), "f"(m.z), "f"(m.w) : "memory"); \
        }

        int cnt = E - e0; if (cnt > 32) cnt = 32;
        if (cnt == 32) {
            #pragma unroll 4
            for (int i = 0; i < 32; i++) EDGE_BODY(i)
        } else {
            for (int i = 0; i < cnt; i++) EDGE_BODY(i)
        }
        #undef EDGE_BODY
    }
}

// ---------------- mma / ldmatrix helpers ----------------------------------------
__device__ __forceinline__ void mma_bf16(float* d, unsigned a0, unsigned a1,
                                         unsigned a2, unsigned a3,
                                         unsigned b0, unsigned b1) {
    asm volatile(
        "mma.sync.aligned.m16n8k16.row.col.f32.bf16.bf16.f32 "
        "{%0,%1,%2,%3}, {%4,%5,%6,%7}, {%8,%9}, {%0,%1,%2,%3};\n"
        : "+f"(d[0]), "+f"(d[1]), "+f"(d[2]), "+f"(d[3])
        : "r"(a0), "r"(a1), "r"(a2), "r"(a3), "r"(b0), "r"(b1));
}

__device__ __forceinline__ void ldsm_x4(unsigned& r0, unsigned& r1,
                                        unsigned& r2, unsigned& r3, unsigned addr) {
    asm volatile("ldmatrix.sync.aligned.m8n8.x4.shared.b16 {%0,%1,%2,%3}, [%4];"
                 : "=r"(r0), "=r"(r1), "=r"(r2), "=r"(r3) : "r"(addr));
}

// ---------------- K4: tensor-core GEMM, bf16 3-pass, double-buffered ------------
// Block 128x128, 8 warps (2M x 4N). W tiles pre-packed in g_Wpk (pure copies).
#define PITCHW 20                    // row pitch in words (80 B)
#define BUFW   (128 * PITCHW)        // words per buffer
__global__ __launch_bounds__(256, 2) void k_gemm(const float* __restrict__ x,
                                                 const float* __restrict__ bias,
                                                 float* __restrict__ out, int N) {
    __shared__ unsigned sA[2 * BUFW];
    __shared__ unsigned sW[2 * BUFW];
    __shared__ float inv_s[128];
    __shared__ float scol[128], scolq[128];

    int tid = threadIdx.x;
    int row0 = blockIdx.x * 128;
    if (tid < 128) {
        int r = row0 + tid;
        inv_s[tid] = (r < N) ? (1.f / fmaxf(g_cnt[r], 1.f)) : 0.f;
        scol[tid] = 0.f; scolq[tid] = 0.f;
    }

    int lane  = tid & 31;
    int warp  = tid >> 5;
    int warpM = warp >> 2;
    int warpN = warp & 3;
    int grp   = lane >> 2;
    int th4   = lane & 3;

    unsigned sA_base = (unsigned)__cvta_generic_to_shared(sA);
    unsigned sW_base = (unsigned)__cvta_generic_to_shared(sW);
    unsigned aAddr = sA_base + (unsigned)((warpM * 64 + (lane & 15)) * 80 + (lane >> 4) * 16);
    int quad = lane >> 3;
    unsigned bAddr = sW_base + (unsigned)((warpN * 32 + ((quad >> 1) * 8) + (lane & 7)) * 80
                                          + (quad & 1) * 16);

    float c[4][4][4];
    #pragma unroll
    for (int mi = 0; mi < 4; mi++)
        #pragma unroll
        for (int ni = 0; ni < 4; ni++)
            #pragma unroll
            for (int j = 0; j < 4; j++) c[mi][ni][j] = 0.f;

    int a_m0 = tid >> 2, a_ch = tid & 3;
    int w_row = tid >> 1, w_half = tid & 1;

    __syncthreads();   // inv_s ready

    float4 av[2]; uint4 wq0, wq1;

    #define LOAD_TILE(kt)                                                             \
    {                                                                                 \
        _Pragma("unroll")                                                             \
        for (int u = 0; u < 2; u++) {                                                 \
            int m = a_m0 + u * 64;                                                    \
            int r = row0 + m;                                                         \
            av[u] = make_float4(0.f, 0.f, 0.f, 0.f);                                  \
            if (r < N) {                                                              \
                if ((kt) < 8) {                                                       \
                    av[u] = *reinterpret_cast<const float4*>(x + (size_t)r * D + (kt) * 16 + a_ch * 4); \
                } else {                                                              \
                    float iv = inv_s[m];                                              \
                    av[u] = *reinterpret_cast<const float4*>(g_acc + (size_t)r * D + ((kt) - 8) * 16 + a_ch * 4); \
                    av[u].x *= iv; av[u].y *= iv; av[u].z *= iv; av[u].w *= iv;       \
                }                                                                     \
            }                                                                         \
        }                                                                             \
        const unsigned* wsrc = g_Wpk + (kt) * 2048 + w_row * 16 + w_half * 8;         \
        wq0 = *reinterpret_cast<const uint4*>(wsrc);                                  \
        wq1 = *reinterpret_cast<const uint4*>(wsrc + 4);                              \
    }

    #define STAGE_TILE(buf)                                                           \
    {                                                                                 \
        unsigned* dA = sA + (buf) * BUFW;                                             \
        unsigned* dW = sW + (buf) * BUFW;                                             \
        _Pragma("unroll")                                                             \
        for (int u = 0; u < 2; u++) {                                                 \
            int m = a_m0 + u * 64;                                                    \
            float h0, l0, h1, l1, h2, l2, h3, l3;                                     \
            split_bf16(av[u].x, h0, l0);                                              \
            split_bf16(av[u].y, h1, l1);                                              \
            split_bf16(av[u].z, h2, l2);                                              \
            split_bf16(av[u].w, h3, l3);                                              \
            int base = m * PITCHW + a_ch * 2;                                         \
            *reinterpret_cast<uint2*>(&dA[base])     = make_uint2(pack_bf16(h0, h1), pack_bf16(h2, h3)); \
            *reinterpret_cast<uint2*>(&dA[base + 8]) = make_uint2(pack_bf16(l0, l1), pack_bf16(l2, l3)); \
        }                                                                             \
        unsigned* wdst = dW + w_row * PITCHW + w_half * 8;                            \
        *reinterpret_cast<uint4*>(wdst)     = wq0;                                    \
        *reinterpret_cast<uint4*>(wdst + 4) = wq1;                                    \
    }

    LOAD_TILE(0)
    STAGE_TILE(0)
    __syncthreads();

    for (int kt = 0; kt < 16; kt++) {
        if (kt < 15) LOAD_TILE(kt + 1)

        unsigned bufOff = (unsigned)((kt & 1) * BUFW * 4);
        unsigned bH[4][2], bL[4][2];
        #pragma unroll
        for (int p = 0; p < 2; p++) {
            unsigned off = bufOff + (unsigned)(p * 16 * 80);
            ldsm_x4(bH[2*p][0], bH[2*p][1], bH[2*p+1][0], bH[2*p+1][1], bAddr + off);
            ldsm_x4(bL[2*p][0], bL[2*p][1], bL[2*p+1][0], bL[2*p+1][1], bAddr + off + 32);
        }
        #pragma unroll
        for (int mi = 0; mi < 4; mi++) {
            unsigned off = bufOff + (unsigned)(mi * 16 * 80);
            unsigned aH0, aH1, aH2, aH3, aL0, aL1, aL2, aL3;
            ldsm_x4(aH0, aH1, aH2, aH3, aAddr + off);
            ldsm_x4(aL0, aL1, aL2, aL3, aAddr + off + 32);
            #pragma unroll
            for (int ni = 0; ni < 4; ni++) {
                mma_bf16(c[mi][ni], aH0, aH1, aH2, aH3, bH[ni][0], bH[ni][1]);
                mma_bf16(c[mi][ni], aH0, aH1, aH2, aH3, bL[ni][0], bL[ni][1]);
                mma_bf16(c[mi][ni], aL0, aL1, aL2, aL3, bH[ni][0], bH[ni][1]);
            }
        }

        if (kt < 15) STAGE_TILE((kt + 1) & 1)
        __syncthreads();
    }
    #undef LOAD_TILE
    #undef STAGE_TILE

    // ---- epilogue: bias + store + BN stats ----
    float ss[4][2], qq[4][2];
    #pragma unroll
    for (int ni = 0; ni < 4; ni++) { ss[ni][0]=ss[ni][1]=qq[ni][0]=qq[ni][1]=0.f; }

    #pragma unroll
    for (int ni = 0; ni < 4; ni++) {
        int col = warpN * 32 + ni * 8 + 2 * th4;
        float b0 = __ldg(bias + col), b1 = __ldg(bias + col + 1);
        #pragma unroll
        for (int mi = 0; mi < 4; mi++) {
            int rlo = row0 + warpM * 64 + mi * 16 + grp;
            if (rlo < N) {
                float v0 = c[mi][ni][0] + b0;
                float v1 = c[mi][ni][1] + b1;
                *reinterpret_cast<float2*>(out + (size_t)rlo * D + col) = make_float2(v0, v1);
                ss[ni][0] += v0; qq[ni][0] += v0 * v0;
                ss[ni][1] += v1; qq[ni][1] += v1 * v1;
            }
            int rhi = rlo + 8;
            if (rhi < N) {
                float v2 = c[mi][ni][2] + b0;
                float v3 = c[mi][ni][3] + b1;
                *reinterpret_cast<float2*>(out + (size_t)rhi * D + col) = make_float2(v2, v3);
                ss[ni][0] += v2; qq[ni][0] += v2 * v2;
                ss[ni][1] += v3; qq[ni][1] += v3 * v3;
            }
        }
    }
    #pragma unroll
    for (int ni = 0; ni < 4; ni++)
        #pragma unroll
        for (int j = 0; j < 2; j++) {
            float s = ss[ni][j], q = qq[ni][j];
            #pragma unroll
            for (int off = 4; off < 32; off <<= 1) {
                s += __shfl_xor_sync(0xffffffffu, s, off);
                q += __shfl_xor_sync(0xffffffffu, q, off);
            }
            if (lane < 4) {
                int col = warpN * 32 + ni * 8 + 2 * lane + j;
                atomicAdd(&scol[col],  s);
                atomicAdd(&scolq[col], q);
            }
        }
    __syncthreads();
    if (tid < D) {
        atomicAdd(&g_colsum[tid], scol[tid]);
        atomicAdd(&g_colsq[tid],  scolq[tid]);
    }
}

// ---------------- K5: BN finalize + relu + residual -----------------------------
__global__ void k_bn(const float* __restrict__ x, const float* __restrict__ gamma,
                     const float* __restrict__ beta, float* __restrict__ out, int N) {
    __shared__ float ssc[D], ssh[D];
    int t = threadIdx.x;
    if (t < D) {
        float invN = 1.f / (float)N;
        float mean = g_colsum[t] * invN;
        float var  = g_colsq[t] * invN - mean * mean;
        float sc = gamma[t] * rsqrtf(var + 1e-5f);
        ssc[t] = sc;
        ssh[t] = beta[t] - mean * sc;
    }
    __syncthreads();
    int i = blockIdx.x * blockDim.x + t;
    int tot = N * (D / 4);
    if (i < tot) {
        int c = (i & 31) * 4;
        float4 o  = reinterpret_cast<float4*>(out)[i];
        float4 xr = reinterpret_cast<const float4*>(x)[i];
        o.x = fmaxf(fmaf(o.x, ssc[c + 0], ssh[c + 0]), 0.f) + xr.x;
        o.y = fmaxf(fmaf(o.y, ssc[c + 1], ssh[c + 1]), 0.f) + xr.y;
        o.z = fmaxf(fmaf(o.z, ssc[c + 2], ssh[c + 2]), 0.f) + xr.z;
        o.w = fmaxf(fmaf(o.w, ssc[c + 3], ssh[c + 3]), 0.f) + xr.w;
        reinterpret_cast<float4*>(out)[i] = o;
    }
}

// ---------------- launch --------------------------------------------------------
extern "C" void kernel_launch(void* const* d_in, const int* in_sizes, int n_in,
                              void* d_out, int out_size) {
    const float* x     = (const float*)d_in[0];
    const void*  ei    = d_in[1];
    const float* ew    = (const float*)d_in[2];
    const float* pw1   = (const float*)d_in[3];
    const float* pw2   = (const float*)d_in[4];
    const float* sw    = (const float*)d_in[5];
    const float* sb    = (const float*)d_in[6];
    const float* gamma = (const float*)d_in[7];
    const float* beta  = (const float*)d_in[8];
    float* out = (float*)d_out;

    int N = in_sizes[0] / D;
    int E = in_sizes[1] / 2;

    k_zero<<<4096, 256>>>((const int*)ei, N);
    k_sectors<<<SECT, 256>>>(pw1, pw2);
    k_wprep<<<64, 256>>>(sw);
    k_edges<<<4096, 256>>>(x, ei, ew, E);
    k_gemm<<<(N + 127) / 128, 256>>>(x, sb, out, N);
    k_bn<<<(N * (D / 4) + 255) / 256, 256>>>(x, gamma, beta, out, N);
}